// round 1
// baseline (speedup 1.0000x reference)
#include <cuda_runtime.h>
#include <cuda_bf16.h>

// Problem constants (fixed by reference)
#define BATCH   2
#define SEQ     512
#define DMODEL  512
#define NHEADS  8
#define DK      64
#define BL      (BATCH*SEQ)   // 1024 rows

// ---------------- scratch (device globals; no allocation allowed) ----------
__device__ float g_WqE[DMODEL*DMODEL];
__device__ float g_WkE[DMODEL*DMODEL];
__device__ float g_WvT[DMODEL*DMODEL];
__device__ float g_WoT[DMODEL*DMODEL];
__device__ float g_bqE[DMODEL];
__device__ float g_bkE[DMODEL];
__device__ float g_qp[BL*DMODEL];
__device__ float g_kp[BL*DMODEL];
__device__ float g_V [BL*DMODEL];
__device__ float g_att[BL*DMODEL];

__device__ __forceinline__ float tanh_fast(float x) {
    float y;
    asm("tanh.approx.f32 %0, %1;" : "=f"(y) : "f"(x));
    return y;
}

// ---------------------------------------------------------------------------
// Fold inner per-head projection into outer weight:
//   Wq_eff[i][h*64+d'] = sum_d Wq[(h*64+d)*512 + i] * Aq[d'*64 + d]
// (so  qp = query @ Wq_eff + bq_eff  gives  (query@Wq.T+bq)@Aq.T per head)
// ---------------------------------------------------------------------------
__global__ void prep_w_eff(const float* __restrict__ Wq, const float* __restrict__ Aq,
                           const float* __restrict__ Wk, const float* __restrict__ Ak) {
    int p = blockIdx.x * blockDim.x + threadIdx.x;   // 0 .. 2*512*512-1
    int sel = p >> 18;
    int rem = p & 262143;
    int i = rem >> 9;
    int o = rem & 511;
    int h = o >> 6, dp = o & 63;
    const float* W = sel ? Wk : Wq;
    const float* A = sel ? Ak : Aq;
    float s = 0.f;
#pragma unroll 8
    for (int d = 0; d < 64; d++)
        s += W[(h*64 + d)*DMODEL + i] * A[dp*64 + d];
    (sel ? g_WkE : g_WqE)[i*DMODEL + o] = s;
}

__global__ void prep_b_eff(const float* __restrict__ bq, const float* __restrict__ Aq,
                           const float* __restrict__ bk, const float* __restrict__ Ak) {
    int p = blockIdx.x * blockDim.x + threadIdx.x;   // 0..1023
    if (p >= 2*DMODEL) return;
    int sel = p >> 9;
    int o = p & 511;
    int h = o >> 6, dp = o & 63;
    const float* b = sel ? bk : bq;
    const float* A = sel ? Ak : Aq;
    float s = 0.f;
#pragma unroll 8
    for (int d = 0; d < 64; d++)
        s += b[h*64 + d] * A[dp*64 + d];
    (sel ? g_bkE : g_bqE)[o] = s;
}

// Transpose Wv, Wo (torch Linear weights are [out,in]; GEMM wants B[k][n]).
__global__ void transpose2(const float* __restrict__ Wv, const float* __restrict__ Wo) {
    int p = blockIdx.x * blockDim.x + threadIdx.x;   // 0..2*512*512-1
    int sel = p >> 18;
    int rem = p & 262143;
    int r = rem >> 9, c = rem & 511;
    const float* src = sel ? Wo : Wv;
    float* dst = sel ? g_WoT : g_WvT;
    dst[c*DMODEL + r] = src[r*DMODEL + c];
}

// ---------------------------------------------------------------------------
// C[M,N] = A[M,K] @ B[K,N] + bias[N].  M=1024, N=K=512. 64x64 tile, 4x4/thread.
// ---------------------------------------------------------------------------
__global__ void gemm_bias(const float* __restrict__ A, const float* __restrict__ Bm,
                          const float* __restrict__ bias, float* __restrict__ C) {
    const int K = DMODEL, N = DMODEL;
    __shared__ float As[16][64];   // [k][m]
    __shared__ float Bs[16][64];   // [k][n]
    int t  = threadIdx.x;          // 256
    int bm = blockIdx.y * 64;
    int bn = blockIdx.x * 64;
    int tx = t & 15, ty = t >> 4;

    float acc[4][4];
#pragma unroll
    for (int i = 0; i < 4; i++)
#pragma unroll
        for (int j = 0; j < 4; j++) acc[i][j] = 0.f;

    int a_row = t >> 2;            // 0..63
    int a_c4  = (t & 3) << 2;      // 0,4,8,12
    int b_row = t >> 4;            // 0..15
    int b_c4  = (t & 15) << 2;

    const float* Aptr = A  + (long)(bm + a_row) * K + a_c4;
    const float* Bptr = Bm + (long)b_row * N + bn + b_c4;

    for (int k0 = 0; k0 < K; k0 += 16) {
        float4 a4 = *(const float4*)Aptr;  Aptr += 16;
        float4 b4 = *(const float4*)Bptr;  Bptr += 16 * N;
        As[a_c4+0][a_row] = a4.x;
        As[a_c4+1][a_row] = a4.y;
        As[a_c4+2][a_row] = a4.z;
        As[a_c4+3][a_row] = a4.w;
        *(float4*)&Bs[b_row][b_c4] = b4;
        __syncthreads();
#pragma unroll
        for (int k = 0; k < 16; k++) {
            float4 av4 = *(const float4*)&As[k][ty*4];
            float4 bv4 = *(const float4*)&Bs[k][tx*4];
            float aa[4] = {av4.x, av4.y, av4.z, av4.w};
            float bb[4] = {bv4.x, bv4.y, bv4.z, bv4.w};
#pragma unroll
            for (int i = 0; i < 4; i++)
#pragma unroll
                for (int j = 0; j < 4; j++)
                    acc[i][j] += aa[i] * bb[j];
        }
        __syncthreads();
    }
#pragma unroll
    for (int i = 0; i < 4; i++) {
        int row = bm + ty*4 + i;
        float4 o;
        o.x = acc[i][0] + bias[bn + tx*4 + 0];
        o.y = acc[i][1] + bias[bn + tx*4 + 1];
        o.z = acc[i][2] + bias[bn + tx*4 + 2];
        o.w = acc[i][3] + bias[bn + tx*4 + 3];
        *(float4*)&C[(long)row*N + bn + tx*4] = o;
    }
}

// ---------------------------------------------------------------------------
// Attention: per (b,h, 32-query tile):
//   scores[i][j] = sum_d av[d]*tanh(qp[i][d]+kp[j][d]);  softmax_j;  out = P@V
// smem: sk[64][68] (kp/V tile), sc[32][516] (score row), s_av[64], s_scale[32]
// ---------------------------------------------------------------------------
#define SK_LD 68
#define SC_LD 516
#define ATTN_SMEM ((64*SK_LD + 32*SC_LD + 64 + 32) * 4)

__global__ void attn_kernel(const float* __restrict__ qp, const float* __restrict__ kp,
                            const float* __restrict__ V,  const float* __restrict__ av,
                            float* __restrict__ out) {
    extern __shared__ float sm[];
    float* sk      = sm;                     // 64 x 68
    float* sc      = sm + 64*SK_LD;          // 32 x 516
    float* s_av    = sc + 32*SC_LD;          // 64
    float* s_scale = s_av + 64;              // 32

    int t    = threadIdx.x;                  // 256
    int lane = t & 31;
    int wid  = t >> 5;
    int i0   = blockIdx.x * 32;
    int bh   = blockIdx.y;
    int b    = bh >> 3, h = bh & 7;
    const int h64 = h * 64;
    const long rowbase = (long)b * SEQ;

    if (t < 64) s_av[t] = av[t];

    // cache this thread's query row (i = lane) in registers
    float q_r[64];
    {
        const float* qrow = qp + (rowbase + i0 + lane) * DMODEL + h64;
#pragma unroll
        for (int d = 0; d < 64; d += 4) {
            float4 v4 = *(const float4*)(qrow + d);
            q_r[d] = v4.x; q_r[d+1] = v4.y; q_r[d+2] = v4.z; q_r[d+3] = v4.w;
        }
    }
    __syncthreads();

    // ---- phase 1: scores ----
    for (int jt = 0; jt < SEQ; jt += 64) {
        for (int idx = t; idx < 64*64; idx += 256) {
            int j = idx >> 6, c = idx & 63;
            sk[j*SK_LD + c] = kp[(rowbase + jt + j) * DMODEL + h64 + c];
        }
        __syncthreads();
#pragma unroll
        for (int jj = 0; jj < 8; jj++) {
            int j = wid * 8 + jj;            // all lanes of a warp share j -> broadcast
            const float* krow = &sk[j*SK_LD];
            float s = 0.f;
#pragma unroll
            for (int d = 0; d < 64; d += 4) {
                float4 k4 = *(const float4*)(krow + d);
                float4 a4 = *(const float4*)(&s_av[d]);
                s += a4.x * tanh_fast(q_r[d+0] + k4.x);
                s += a4.y * tanh_fast(q_r[d+1] + k4.y);
                s += a4.z * tanh_fast(q_r[d+2] + k4.z);
                s += a4.w * tanh_fast(q_r[d+3] + k4.w);
            }
            sc[lane*SC_LD + jt + j] = s;
        }
        __syncthreads();
    }

    // ---- phase 2: softmax (8 warps x 4 rows) ----
#pragma unroll
    for (int r = 0; r < 4; r++) {
        int ri = wid * 4 + r;
        float m = -1e30f;
        for (int c = lane; c < SEQ; c += 32)
            m = fmaxf(m, sc[ri*SC_LD + c]);
#pragma unroll
        for (int o = 16; o; o >>= 1) m = fmaxf(m, __shfl_xor_sync(~0u, m, o));
        float sum = 0.f;
        for (int c = lane; c < SEQ; c += 32) {
            float p = __expf(sc[ri*SC_LD + c] - m);
            sc[ri*SC_LD + c] = p;
            sum += p;
        }
#pragma unroll
        for (int o = 16; o; o >>= 1) sum += __shfl_xor_sync(~0u, sum, o);
        if (lane == 0) s_scale[ri] = 1.f / sum;
    }
    __syncthreads();

    // ---- phase 3: out = P @ V ----
    int d  = t & 63;
    int ig = t >> 6;                         // 0..3, each handles 8 queries
    float acc[8];
#pragma unroll
    for (int z = 0; z < 8; z++) acc[z] = 0.f;

    for (int jt = 0; jt < SEQ; jt += 64) {
        for (int idx = t; idx < 64*64; idx += 256) {
            int j = idx >> 6, c = idx & 63;
            sk[j*SK_LD + c] = V[(rowbase + jt + j) * DMODEL + h64 + c];
        }
        __syncthreads();
#pragma unroll
        for (int ii = 0; ii < 8; ii++) {
            int i = ig * 8 + ii;
            const float* prow = &sc[i*SC_LD + jt];
            float a = acc[ii];
#pragma unroll 16
            for (int j = 0; j < 64; j++)
                a += prow[j] * sk[j*SK_LD + d];
            acc[ii] = a;
        }
        __syncthreads();
    }
#pragma unroll
    for (int ii = 0; ii < 8; ii++) {
        int i = ig * 8 + ii;
        out[(rowbase + i0 + i) * DMODEL + h64 + d] = acc[ii] * s_scale[i];
    }
}

// ---------------------------------------------------------------------------
extern "C" void kernel_launch(void* const* d_in, const int* in_sizes, int n_in,
                              void* d_out, int out_size) {
    const float* query = (const float*)d_in[0];
    const float* key   = (const float*)d_in[1];
    const float* value = (const float*)d_in[2];
    const float* Wq    = (const float*)d_in[3];
    const float* bq    = (const float*)d_in[4];
    const float* Wk    = (const float*)d_in[5];
    const float* bk    = (const float*)d_in[6];
    const float* Wv    = (const float*)d_in[7];
    const float* bv    = (const float*)d_in[8];
    const float* Wo    = (const float*)d_in[9];
    const float* bo    = (const float*)d_in[10];
    const float* Aq    = (const float*)d_in[11];
    const float* Ak    = (const float*)d_in[12];
    const float* av    = (const float*)d_in[13];
    float* out = (float*)d_out;

    float *pWqE, *pWkE, *pWvT, *pWoT, *pbqE, *pbkE, *pqp, *pkp, *pV, *patt;
    cudaGetSymbolAddress((void**)&pWqE, g_WqE);
    cudaGetSymbolAddress((void**)&pWkE, g_WkE);
    cudaGetSymbolAddress((void**)&pWvT, g_WvT);
    cudaGetSymbolAddress((void**)&pWoT, g_WoT);
    cudaGetSymbolAddress((void**)&pbqE, g_bqE);
    cudaGetSymbolAddress((void**)&pbkE, g_bkE);
    cudaGetSymbolAddress((void**)&pqp,  g_qp);
    cudaGetSymbolAddress((void**)&pkp,  g_kp);
    cudaGetSymbolAddress((void**)&pV,   g_V);
    cudaGetSymbolAddress((void**)&patt, g_att);

    cudaFuncSetAttribute(attn_kernel, cudaFuncAttributeMaxDynamicSharedMemorySize, ATTN_SMEM);

    prep_w_eff<<<2048, 256>>>(Wq, Aq, Wk, Ak);
    prep_b_eff<<<4, 256>>>(bq, Aq, bk, Ak);
    transpose2<<<2048, 256>>>(Wv, Wo);

    dim3 gg(DMODEL/64, BL/64);   // (8,16)
    gemm_bias<<<gg, 256>>>(query, pWqE, pbqE, pqp);
    gemm_bias<<<gg, 256>>>(key,   pWkE, pbkE, pkp);
    gemm_bias<<<gg, 256>>>(value, pWvT, bv,   pV);

    attn_kernel<<<dim3(SEQ/32, BATCH*NHEADS), 256, ATTN_SMEM>>>(pqp, pkp, pV, av, patt);

    gemm_bias<<<gg, 256>>>(patt, pWoT, bo, out);
}

// round 2
// speedup vs baseline: 1.2050x; 1.2050x over previous
#include <cuda_runtime.h>
#include <cuda_bf16.h>

// Problem constants (fixed by reference)
#define BATCH   2
#define SEQ     512
#define DMODEL  512
#define NHEADS  8
#define DK      64
#define BL      (BATCH*SEQ)   // 1024 rows

// ---------------- scratch (device globals; no allocation allowed) ----------
__device__ float g_WqE[DMODEL*DMODEL];
__device__ float g_WkE[DMODEL*DMODEL];
__device__ float g_WvT[DMODEL*DMODEL];
__device__ float g_WoT[DMODEL*DMODEL];
__device__ float g_bqE[DMODEL];
__device__ float g_bkE[DMODEL];
__device__ float g_qp[BL*DMODEL];
__device__ float g_kp[BL*DMODEL];
__device__ float g_V [BL*DMODEL];
__device__ float g_att[BL*DMODEL];

__device__ __forceinline__ float tanh_fast(float x) {
    float y;
    asm("tanh.approx.f32 %0, %1;" : "=f"(y) : "f"(x));
    return y;
}

// ---------------------------------------------------------------------------
// Fused prep: effective weights (fold Aq/Ak into Wq/Wk), transposes, eff biases
//   Wq_eff[i][h*64+d'] = sum_d Wq[(h*64+d)*512 + i] * Aq[d'*64 + d]
// ---------------------------------------------------------------------------
__global__ void prep_all(const float* __restrict__ Wq, const float* __restrict__ Aq,
                         const float* __restrict__ Wk, const float* __restrict__ Ak,
                         const float* __restrict__ Wv, const float* __restrict__ Wo,
                         const float* __restrict__ bq, const float* __restrict__ bk) {
    int p = blockIdx.x * blockDim.x + threadIdx.x;
    if (p < 2*DMODEL*DMODEL) {
        int sel = p >> 18;
        int rem = p & 262143;
        int i = rem >> 9;
        int o = rem & 511;
        int h = o >> 6, dp = o & 63;
        const float* W = sel ? Wk : Wq;
        const float* A = sel ? Ak : Aq;
        float s = 0.f;
#pragma unroll 8
        for (int d = 0; d < 64; d++)
            s += W[(h*64 + d)*DMODEL + i] * A[dp*64 + d];
        (sel ? g_WkE : g_WqE)[i*DMODEL + o] = s;
    } else if (p < 4*DMODEL*DMODEL) {
        int sel = (p >> 18) & 1;
        int rem = p & 262143;
        int r = rem >> 9, c = rem & 511;
        const float* src = sel ? Wo : Wv;
        float* dst = sel ? g_WoT : g_WvT;
        dst[c*DMODEL + r] = src[r*DMODEL + c];
    } else {
        int q = p - 4*DMODEL*DMODEL;
        if (q < 2*DMODEL) {
            int sel = q >> 9;
            int o = q & 511;
            int h = o >> 6, dp = o & 63;
            const float* b = sel ? bk : bq;
            const float* A = sel ? Ak : Aq;
            float s = 0.f;
#pragma unroll 8
            for (int d = 0; d < 64; d++)
                s += b[h*64 + d] * A[dp*64 + d];
            (sel ? g_bkE : g_bqE)[o] = s;
        }
    }
}

// ---------------------------------------------------------------------------
// C[M,N] = A[M,K] @ B[K,N] + bias[N].  M=1024, N=K=512.
// 64x64 tile, 128 threads, 8x4 microtile, double-buffered smem.
// Up to 3 independent GEMMs selected by blockIdx.z.
// ---------------------------------------------------------------------------
#define GBK 16
#define ASTR 68

__global__ __launch_bounds__(128) void gemm_v2(
    const float* __restrict__ A0, const float* __restrict__ B0,
    const float* __restrict__ c0, float* __restrict__ C0,
    const float* __restrict__ A1, const float* __restrict__ B1,
    const float* __restrict__ c1, float* __restrict__ C1,
    const float* __restrict__ A2, const float* __restrict__ B2,
    const float* __restrict__ c2, float* __restrict__ C2) {
    const int K = DMODEL, N = DMODEL;
    const float* A = A0; const float* Bm = B0; const float* bias = c0; float* C = C0;
    if (blockIdx.z == 1) { A = A1; Bm = B1; bias = c1; C = C1; }
    else if (blockIdx.z == 2) { A = A2; Bm = B2; bias = c2; C = C2; }

    __shared__ float As[2][GBK*ASTR];
    __shared__ float Bs[2][GBK*64];

    int t  = threadIdx.x;          // 128
    int bm = blockIdx.y * 64;
    int bn = blockIdx.x * 64;
    int tx = t & 15, ty = t >> 4;  // tx: 16 (N), ty: 8 (M)

    float acc[8][4];
#pragma unroll
    for (int i = 0; i < 8; i++)
#pragma unroll
        for (int j = 0; j < 4; j++) acc[i][j] = 0.f;

    const float* Ab = A + bm * K;
    const float* Bb = Bm + bn;

    float4 ra[2], rb[2];

    auto fetch = [&](int k0) {
#pragma unroll
        for (int r = 0; r < 2; r++) {
            int idx = t*2 + r;
            ra[r] = *(const float4*)(Ab + (idx >> 2) * K + k0 + ((idx & 3) << 2));
            rb[r] = *(const float4*)(Bb + (k0 + (idx >> 4)) * N + ((idx & 15) << 2));
        }
    };
    auto stage = [&](int buf) {
#pragma unroll
        for (int r = 0; r < 2; r++) {
            int idx = t*2 + r;
            int arow = idx >> 2, ac4 = (idx & 3) << 2;
            As[buf][(ac4+0)*ASTR + arow] = ra[r].x;
            As[buf][(ac4+1)*ASTR + arow] = ra[r].y;
            As[buf][(ac4+2)*ASTR + arow] = ra[r].z;
            As[buf][(ac4+3)*ASTR + arow] = ra[r].w;
            *(float4*)&Bs[buf][(idx >> 4)*64 + ((idx & 15) << 2)] = rb[r];
        }
    };

    fetch(0);
    stage(0);
    int cur = 0;
    for (int k0 = 0; k0 < K; k0 += GBK) {
        __syncthreads();
        bool more = (k0 + GBK) < K;
        if (more) fetch(k0 + GBK);
#pragma unroll
        for (int k = 0; k < GBK; k++) {
            float4 aA = *(const float4*)&As[cur][k*ASTR + ty*8];
            float4 aB = *(const float4*)&As[cur][k*ASTR + ty*8 + 4];
            float4 bb = *(const float4*)&Bs[cur][k*64 + tx*4];
            float am[8] = {aA.x, aA.y, aA.z, aA.w, aB.x, aB.y, aB.z, aB.w};
            float bv[4] = {bb.x, bb.y, bb.z, bb.w};
#pragma unroll
            for (int i = 0; i < 8; i++)
#pragma unroll
                for (int j = 0; j < 4; j++)
                    acc[i][j] += am[i] * bv[j];
        }
        if (more) stage(cur ^ 1);
        cur ^= 1;
    }

    float4 bvec = *(const float4*)(bias + bn + tx*4);
#pragma unroll
    for (int i = 0; i < 8; i++) {
        int row = bm + ty*8 + i;
        float4 o;
        o.x = acc[i][0] + bvec.x;
        o.y = acc[i][1] + bvec.y;
        o.z = acc[i][2] + bvec.z;
        o.w = acc[i][3] + bvec.w;
        *(float4*)&C[row*N + bn + tx*4] = o;
    }
}

// ---------------------------------------------------------------------------
// Attention: per (b,h, 32-query tile):
//   scores[i][j] = sum_d av[d]*tanh(qp[i][d]+kp[j][d]);  softmax_j;  out = P@V
// smem: sk[64][68] (kp/V tile), sc[32][516] (score row), s_av[64], s_scale[32]
// ---------------------------------------------------------------------------
#define SK_LD 68
#define SC_LD 516
#define ATTN_SMEM ((64*SK_LD + 32*SC_LD + 64 + 32) * 4)

__global__ void attn_kernel(const float* __restrict__ qp, const float* __restrict__ kp,
                            const float* __restrict__ V,  const float* __restrict__ av,
                            float* __restrict__ out) {
    extern __shared__ float sm[];
    float* sk      = sm;                     // 64 x 68
    float* sc      = sm + 64*SK_LD;          // 32 x 516
    float* s_av    = sc + 32*SC_LD;          // 64
    float* s_scale = s_av + 64;              // 32

    int t    = threadIdx.x;                  // 256
    int lane = t & 31;
    int wid  = t >> 5;
    int i0   = blockIdx.x * 32;
    int bh   = blockIdx.y;
    int b    = bh >> 3, h = bh & 7;
    const int h64 = h * 64;
    const int rowbase = b * SEQ;

    if (t < 64) s_av[t] = av[t];

    // cache this thread's query row (i = lane) in registers
    float q_r[64];
    {
        const float* qrow = qp + (rowbase + i0 + lane) * DMODEL + h64;
#pragma unroll
        for (int d = 0; d < 64; d += 4) {
            float4 v4 = *(const float4*)(qrow + d);
            q_r[d] = v4.x; q_r[d+1] = v4.y; q_r[d+2] = v4.z; q_r[d+3] = v4.w;
        }
    }
    __syncthreads();

    // ---- phase 1: scores (MUFU-bound) ----
    for (int jt = 0; jt < SEQ; jt += 64) {
        for (int idx = t; idx < 64*64; idx += 256) {
            int j = idx >> 6, c = idx & 63;
            sk[j*SK_LD + c] = kp[(rowbase + jt + j) * DMODEL + h64 + c];
        }
        __syncthreads();
#pragma unroll
        for (int jj = 0; jj < 8; jj++) {
            int j = wid * 8 + jj;            // all lanes of a warp share j -> broadcast
            const float* krow = &sk[j*SK_LD];
            float s = 0.f;
#pragma unroll
            for (int d = 0; d < 64; d += 4) {
                float4 k4 = *(const float4*)(krow + d);
                float4 a4 = *(const float4*)(&s_av[d]);
                s += a4.x * tanh_fast(q_r[d+0] + k4.x);
                s += a4.y * tanh_fast(q_r[d+1] + k4.y);
                s += a4.z * tanh_fast(q_r[d+2] + k4.z);
                s += a4.w * tanh_fast(q_r[d+3] + k4.w);
            }
            sc[lane*SC_LD + jt + j] = s;
        }
        __syncthreads();
    }

    // ---- phase 2: softmax (8 warps x 4 rows) ----
#pragma unroll
    for (int r = 0; r < 4; r++) {
        int ri = wid * 4 + r;
        float m = -1e30f;
        for (int c = lane; c < SEQ; c += 32)
            m = fmaxf(m, sc[ri*SC_LD + c]);
#pragma unroll
        for (int o = 16; o; o >>= 1) m = fmaxf(m, __shfl_xor_sync(~0u, m, o));
        float sum = 0.f;
        for (int c = lane; c < SEQ; c += 32) {
            float p = __expf(sc[ri*SC_LD + c] - m);
            sc[ri*SC_LD + c] = p;
            sum += p;
        }
#pragma unroll
        for (int o = 16; o; o >>= 1) sum += __shfl_xor_sync(~0u, sum, o);
        if (lane == 0) s_scale[ri] = 1.f / sum;
    }
    __syncthreads();

    // ---- phase 3: out = P @ V  (register-tiled: 2 queries x 4 d per thread) ----
    int dt = t & 15, ig = t >> 4;            // dt: 16 d-slots, ig: 16 i-slots
    int d4 = dt << 2;
    int ia = ig << 1;                        // queries ia, ia+1
    float acc0[4] = {0.f, 0.f, 0.f, 0.f};
    float acc1[4] = {0.f, 0.f, 0.f, 0.f};

    for (int jt = 0; jt < SEQ; jt += 64) {
        for (int idx = t; idx < 64*64; idx += 256) {
            int j = idx >> 6, c = idx & 63;
            sk[j*SK_LD + c] = V[(rowbase + jt + j) * DMODEL + h64 + c];
        }
        __syncthreads();
        const float* p0 = &sc[ia*SC_LD + jt];
        const float* p1 = &sc[(ia+1)*SC_LD + jt];
#pragma unroll 8
        for (int j = 0; j < 64; j++) {
            float4 v = *(const float4*)&sk[j*SK_LD + d4];
            float pa = p0[j];
            float pb = p1[j];
            acc0[0] += pa * v.x; acc0[1] += pa * v.y;
            acc0[2] += pa * v.z; acc0[3] += pa * v.w;
            acc1[0] += pb * v.x; acc1[1] += pb * v.y;
            acc1[2] += pb * v.z; acc1[3] += pb * v.w;
        }
        __syncthreads();
    }
    float s0 = s_scale[ia], s1 = s_scale[ia+1];
    float4 o0, o1;
    o0.x = acc0[0]*s0; o0.y = acc0[1]*s0; o0.z = acc0[2]*s0; o0.w = acc0[3]*s0;
    o1.x = acc1[0]*s1; o1.y = acc1[1]*s1; o1.z = acc1[2]*s1; o1.w = acc1[3]*s1;
    *(float4*)&out[(rowbase + i0 + ia    ) * DMODEL + h64 + d4] = o0;
    *(float4*)&out[(rowbase + i0 + ia + 1) * DMODEL + h64 + d4] = o1;
}

// ---------------------------------------------------------------------------
extern "C" void kernel_launch(void* const* d_in, const int* in_sizes, int n_in,
                              void* d_out, int out_size) {
    const float* query = (const float*)d_in[0];
    const float* key   = (const float*)d_in[1];
    const float* value = (const float*)d_in[2];
    const float* Wq    = (const float*)d_in[3];
    const float* bq    = (const float*)d_in[4];
    const float* Wk    = (const float*)d_in[5];
    const float* bk    = (const float*)d_in[6];
    const float* Wv    = (const float*)d_in[7];
    const float* bv    = (const float*)d_in[8];
    const float* Wo    = (const float*)d_in[9];
    const float* bo    = (const float*)d_in[10];
    const float* Aq    = (const float*)d_in[11];
    const float* Ak    = (const float*)d_in[12];
    const float* av    = (const float*)d_in[13];
    float* out = (float*)d_out;

    float *pWqE, *pWkE, *pWvT, *pWoT, *pbqE, *pbkE, *pqp, *pkp, *pV, *patt;
    cudaGetSymbolAddress((void**)&pWqE, g_WqE);
    cudaGetSymbolAddress((void**)&pWkE, g_WkE);
    cudaGetSymbolAddress((void**)&pWvT, g_WvT);
    cudaGetSymbolAddress((void**)&pWoT, g_WoT);
    cudaGetSymbolAddress((void**)&pbqE, g_bqE);
    cudaGetSymbolAddress((void**)&pbkE, g_bkE);
    cudaGetSymbolAddress((void**)&pqp,  g_qp);
    cudaGetSymbolAddress((void**)&pkp,  g_kp);
    cudaGetSymbolAddress((void**)&pV,   g_V);
    cudaGetSymbolAddress((void**)&patt, g_att);

    cudaFuncSetAttribute(attn_kernel, cudaFuncAttributeMaxDynamicSharedMemorySize, ATTN_SMEM);

    // prep: 4*512*512 weight elems + 1024 bias elems
    prep_all<<<(4*DMODEL*DMODEL + 2*DMODEL + 255)/256, 256>>>(Wq, Aq, Wk, Ak, Wv, Wo, bq, bk);

    // fused Q/K/V projection GEMMs
    dim3 gg(DMODEL/64, BL/64, 3);   // (8,16,3)
    gemm_v2<<<gg, 128>>>(query, pWqE, pbqE, pqp,
                         key,   pWkE, pbkE, pkp,
                         value, pWvT, bv,   pV);

    attn_kernel<<<dim3(SEQ/32, BATCH*NHEADS), 256, ATTN_SMEM>>>(pqp, pkp, pV, av, patt);

    // output projection
    dim3 go(DMODEL/64, BL/64, 1);
    gemm_v2<<<go, 128>>>(patt, pWoT, bo, out,
                         nullptr, nullptr, nullptr, nullptr,
                         nullptr, nullptr, nullptr, nullptr);
}

// round 7
// speedup vs baseline: 1.8556x; 1.5400x over previous
#include <cuda_runtime.h>
#include <cuda_bf16.h>

// Problem constants (fixed by reference)
#define BATCH   2
#define SEQ     512
#define DMODEL  512
#define NHEADS  8
#define DK      64
#define BL      (BATCH*SEQ)   // 1024 rows

// ---------------- scratch (device globals; no allocation allowed) ----------
__device__ float g_WqE[DMODEL*DMODEL];
__device__ float g_WkE[DMODEL*DMODEL];
__device__ float g_bqE[DMODEL];
__device__ float g_bkE[DMODEL];
__device__ float g_qp[BL*DMODEL];
__device__ float g_kp[BL*DMODEL];
__device__ float g_V [BL*DMODEL];
__device__ float g_att[BL*DMODEL];

__device__ __forceinline__ float tanh_fast(float x) {
    float y;
    asm("tanh.approx.f32 %0, %1;" : "=f"(y) : "f"(x));
    return y;
}

// ---------------------------------------------------------------------------
// Prep: effective weights via tiled mini-GEMMs (coalesced).
//   WE[i][h*64+dp] = sum_d W[(h*64+d)*512 + i] * A[dp*64 + d]
//   bE[h*64+dp]    = sum_d b[h*64+d] * A[dp*64+d]
// grid (8 i-tiles, 8 heads, 2 q/k), 256 threads.
// ---------------------------------------------------------------------------
__global__ __launch_bounds__(256) void prep_eff(
    const float* __restrict__ Wq, const float* __restrict__ Aq,
    const float* __restrict__ Wk, const float* __restrict__ Ak,
    const float* __restrict__ bq, const float* __restrict__ bk) {
    __shared__ float Ws[64*68];   // Ws[d][ii]
    __shared__ float At[64*68];   // At[d][dp]
    int t   = threadIdx.x;
    int it  = blockIdx.x;
    int h   = blockIdx.y;
    int sel = blockIdx.z;
    const float* W = sel ? Wk : Wq;
    const float* A = sel ? Ak : Aq;
    float* WE = sel ? g_WkE : g_WqE;
    const float* bsrc = sel ? bk : bq;
    float* bE = sel ? g_bkE : g_bqE;

    for (int idx = t; idx < 64*64; idx += 256) {
        int d = idx >> 6, ii = idx & 63;
        Ws[d*68 + ii] = W[(h*64 + d)*DMODEL + it*64 + ii];
    }
    for (int idx = t; idx < 64*64; idx += 256) {
        int dp = idx >> 6, d = idx & 63;
        At[d*68 + dp] = A[dp*64 + d];
    }
    __syncthreads();

    int tx = t & 15, ty = t >> 4;
    int dp4 = tx * 4, ii4 = ty * 4;
    float acc[4][4];
#pragma unroll
    for (int i = 0; i < 4; i++)
#pragma unroll
        for (int j = 0; j < 4; j++) acc[i][j] = 0.f;

#pragma unroll 8
    for (int d = 0; d < 64; d++) {
        float4 a4 = *(const float4*)&Ws[d*68 + ii4];
        float4 b4 = *(const float4*)&At[d*68 + dp4];
        float aa[4] = {a4.x, a4.y, a4.z, a4.w};
        float bb[4] = {b4.x, b4.y, b4.z, b4.w};
#pragma unroll
        for (int i = 0; i < 4; i++)
#pragma unroll
            for (int j = 0; j < 4; j++)
                acc[i][j] += aa[i] * bb[j];
    }
#pragma unroll
    for (int i = 0; i < 4; i++) {
        int row = it*64 + ii4 + i;
        *(float4*)&WE[row*DMODEL + h*64 + dp4] =
            make_float4(acc[i][0], acc[i][1], acc[i][2], acc[i][3]);
    }
    // effective bias (once per head)
    if (it == 0 && t < 64) {
        float s = 0.f;
#pragma unroll 8
        for (int d = 0; d < 64; d++)
            s += bsrc[h*64 + d] * At[d*68 + t];
        bE[h*64 + t] = s;
    }
}

// ---------------------------------------------------------------------------
// GEMM v3: C[M,N] = A[M,K] @ B + bias. M=1024, N=K=512.
// 64x64 tile, 256 threads, 4x4 microtile, double-buffered (1 sync / k-tile).
// tb flag: 0 -> B is [K][N] row-major;  1 -> B is [N][K] (torch weight, read
// transposed on the fly). Up to 3 GEMMs via blockIdx.z.
// ---------------------------------------------------------------------------
#define GBK 16

__global__ __launch_bounds__(256) void gemm_v3(
    const float* __restrict__ A0, const float* __restrict__ B0,
    const float* __restrict__ c0, float* __restrict__ C0, int t0,
    const float* __restrict__ A1, const float* __restrict__ B1,
    const float* __restrict__ c1, float* __restrict__ C1, int t1,
    const float* __restrict__ A2, const float* __restrict__ B2,
    const float* __restrict__ c2, float* __restrict__ C2, int t2) {
    const int K = DMODEL, N = DMODEL;
    const float* A = A0; const float* Bm = B0; const float* bias = c0;
    float* C = C0; int tb = t0;
    if (blockIdx.z == 1) { A = A1; Bm = B1; bias = c1; C = C1; tb = t1; }
    else if (blockIdx.z == 2) { A = A2; Bm = B2; bias = c2; C = C2; tb = t2; }

    __shared__ float As[2][GBK*68];
    __shared__ float Bs[2][GBK*68];

    int t  = threadIdx.x;          // 256
    int bm = blockIdx.y * 64;
    int bn = blockIdx.x * 64;
    int tx = t & 15, ty = t >> 4;

    float acc[4][4];
#pragma unroll
    for (int i = 0; i < 4; i++)
#pragma unroll
        for (int j = 0; j < 4; j++) acc[i][j] = 0.f;

    int arow = t >> 2, akc4 = (t & 3) << 2;    // A fetch coords
    int bkrow = t >> 4, bnc4 = (t & 15) << 2;  // B fetch (tb=0)

    float4 ra, rb;
    auto fetch = [&](int k0) {
        ra = *(const float4*)(A + (bm + arow)*K + k0 + akc4);
        if (tb == 0)
            rb = *(const float4*)(Bm + (k0 + bkrow)*N + bn + bnc4);
        else
            rb = *(const float4*)(Bm + (bn + arow)*K + k0 + akc4);
    };
    auto stage = [&](int buf) {
        As[buf][(akc4+0)*68 + arow] = ra.x;
        As[buf][(akc4+1)*68 + arow] = ra.y;
        As[buf][(akc4+2)*68 + arow] = ra.z;
        As[buf][(akc4+3)*68 + arow] = ra.w;
        if (tb == 0) {
            *(float4*)&Bs[buf][bkrow*68 + bnc4] = rb;
        } else {
            Bs[buf][(akc4+0)*68 + arow] = rb.x;
            Bs[buf][(akc4+1)*68 + arow] = rb.y;
            Bs[buf][(akc4+2)*68 + arow] = rb.z;
            Bs[buf][(akc4+3)*68 + arow] = rb.w;
        }
    };

    fetch(0);
    stage(0);
    int cur = 0;
    for (int k0 = 0; k0 < K; k0 += GBK) {
        __syncthreads();
        bool more = (k0 + GBK) < K;
        if (more) fetch(k0 + GBK);
#pragma unroll
        for (int k = 0; k < GBK; k++) {
            float4 a4 = *(const float4*)&As[cur][k*68 + ty*4];
            float4 b4 = *(const float4*)&Bs[cur][k*68 + tx*4];
            float aa[4] = {a4.x, a4.y, a4.z, a4.w};
            float bb[4] = {b4.x, b4.y, b4.z, b4.w};
#pragma unroll
            for (int i = 0; i < 4; i++)
#pragma unroll
                for (int j = 0; j < 4; j++)
                    acc[i][j] += aa[i] * bb[j];
        }
        if (more) stage(cur ^ 1);
        cur ^= 1;
    }

    float4 bvec = *(const float4*)(bias + bn + tx*4);
#pragma unroll
    for (int i = 0; i < 4; i++) {
        int row = bm + ty*4 + i;
        float4 o;
        o.x = acc[i][0] + bvec.x;
        o.y = acc[i][1] + bvec.y;
        o.z = acc[i][2] + bvec.z;
        o.w = acc[i][3] + bvec.w;
        *(float4*)&C[row*N + bn + tx*4] = o;
    }
}

// ---------------------------------------------------------------------------
// Attention (f32 tanh.approx, prefetched tiles):
//   scores[i][j] = sum_d av[d]*tanh(qp[i][d]+kp[j][d]); softmax_j; out = P@V
// ---------------------------------------------------------------------------
#define SK_LD 68
#define SC_LD 513
#define ATTN_SMEM ((64*SK_LD + 32*SC_LD + 64 + 32) * 4)

__global__ __launch_bounds__(256) void attn_kernel(
    const float* __restrict__ qp, const float* __restrict__ kp,
    const float* __restrict__ V,  const float* __restrict__ av,
    float* __restrict__ out) {
    extern __shared__ float sm[];
    float* sk      = sm;                     // 64 x 68 (kp then V tiles)
    float* sc      = sm + 64*SK_LD;          // 32 x 513
    float* s_av    = sc + 32*SC_LD;          // 64
    float* s_scale = s_av + 64;              // 32

    int t    = threadIdx.x;                  // 256
    int lane = t & 31;
    int wid  = t >> 5;
    int i0   = blockIdx.x * 32;
    int bh   = blockIdx.y;
    int b    = bh >> 3, h = bh & 7;
    const int h64 = h * 64;
    const int rowbase = b * SEQ;

    if (t < 64) s_av[t] = av[t];

    // cache this thread's query row (i = lane) in registers
    float q_r[64];
    {
        const float* qrow = qp + (rowbase + i0 + lane) * DMODEL + h64;
#pragma unroll
        for (int d = 0; d < 64; d += 4) {
            float4 v4 = *(const float4*)(qrow + d);
            q_r[d] = v4.x; q_r[d+1] = v4.y; q_r[d+2] = v4.z; q_r[d+3] = v4.w;
        }
    }
    __syncthreads();

    // tile fetch coords: row = t>>2, 16-float chunk = (t&3)*16
    int frow = t >> 2;
    int fc16 = (t & 3) << 4;
    float4 f0, f1, f2, f3;
    auto fetchT = [&](const float* base, int jt) {
        const float* src = base + (rowbase + jt + frow) * DMODEL + h64 + fc16;
        f0 = *(const float4*)(src + 0);
        f1 = *(const float4*)(src + 4);
        f2 = *(const float4*)(src + 8);
        f3 = *(const float4*)(src + 12);
    };
    auto stageT = [&]() {
        float* dst = &sk[frow*SK_LD + fc16];
        *(float4*)(dst + 0)  = f0;
        *(float4*)(dst + 4)  = f1;
        *(float4*)(dst + 8)  = f2;
        *(float4*)(dst + 12) = f3;
    };

    // ---- phase 1: scores (MUFU-bound, f32 tanh) ----
    fetchT(kp, 0);
    for (int jt = 0; jt < SEQ; jt += 64) {
        stageT();
        __syncthreads();
        if (jt + 64 < SEQ) fetchT(kp, jt + 64);
#pragma unroll
        for (int jj = 0; jj < 8; jj++) {
            int j = wid * 8 + jj;            // warp-uniform -> broadcast LDS
            const float* krow = &sk[j*SK_LD];
            float s = 0.f;
#pragma unroll
            for (int d = 0; d < 64; d += 4) {
                float4 k4 = *(const float4*)(krow + d);
                float4 a4 = *(const float4*)(&s_av[d]);
                s += a4.x * tanh_fast(q_r[d+0] + k4.x);
                s += a4.y * tanh_fast(q_r[d+1] + k4.y);
                s += a4.z * tanh_fast(q_r[d+2] + k4.z);
                s += a4.w * tanh_fast(q_r[d+3] + k4.w);
            }
            sc[lane*SC_LD + jt + j] = s;
        }
        __syncthreads();
    }

    // ---- phase 2: softmax (8 warps x 4 rows) ----
#pragma unroll
    for (int r = 0; r < 4; r++) {
        int ri = wid * 4 + r;
        float m = -1e30f;
        for (int c = lane; c < SEQ; c += 32)
            m = fmaxf(m, sc[ri*SC_LD + c]);
#pragma unroll
        for (int o = 16; o; o >>= 1) m = fmaxf(m, __shfl_xor_sync(~0u, m, o));
        float sum = 0.f;
        for (int c = lane; c < SEQ; c += 32) {
            float p = __expf(sc[ri*SC_LD + c] - m);
            sc[ri*SC_LD + c] = p;
            sum += p;
        }
#pragma unroll
        for (int o = 16; o; o >>= 1) sum += __shfl_xor_sync(~0u, sum, o);
        if (lane == 0) s_scale[ri] = 1.f / sum;
    }
    __syncthreads();

    // ---- phase 3: out = P @ V (2 queries x float4 per thread, prefetched) --
    int dt = t & 15, ig = t >> 4;
    int d4 = dt << 2;
    int ia = ig << 1;
    float acc0[4] = {0.f, 0.f, 0.f, 0.f};
    float acc1[4] = {0.f, 0.f, 0.f, 0.f};

    fetchT(V, 0);
    for (int jt = 0; jt < SEQ; jt += 64) {
        stageT();
        __syncthreads();
        if (jt + 64 < SEQ) fetchT(V, jt + 64);
        const float* p0 = &sc[ia*SC_LD + jt];
        const float* p1 = &sc[(ia+1)*SC_LD + jt];
#pragma unroll 8
        for (int j = 0; j < 64; j++) {
            float4 v = *(const float4*)&sk[j*SK_LD + d4];
            float pa = p0[j];
            float pb = p1[j];
            acc0[0] += pa * v.x; acc0[1] += pa * v.y;
            acc0[2] += pa * v.z; acc0[3] += pa * v.w;
            acc1[0] += pb * v.x; acc1[1] += pb * v.y;
            acc1[2] += pb * v.z; acc1[3] += pb * v.w;
        }
        __syncthreads();
    }
    float s0 = s_scale[ia], s1 = s_scale[ia+1];
    float4 o0, o1;
    o0.x = acc0[0]*s0; o0.y = acc0[1]*s0; o0.z = acc0[2]*s0; o0.w = acc0[3]*s0;
    o1.x = acc1[0]*s1; o1.y = acc1[1]*s1; o1.z = acc1[2]*s1; o1.w = acc1[3]*s1;
    *(float4*)&out[(rowbase + i0 + ia    ) * DMODEL + h64 + d4] = o0;
    *(float4*)&out[(rowbase + i0 + ia + 1) * DMODEL + h64 + d4] = o1;
}

// ---------------------------------------------------------------------------
extern "C" void kernel_launch(void* const* d_in, const int* in_sizes, int n_in,
                              void* d_out, int out_size) {
    const float* query = (const float*)d_in[0];
    const float* key   = (const float*)d_in[1];
    const float* value = (const float*)d_in[2];
    const float* Wq    = (const float*)d_in[3];
    const float* bq    = (const float*)d_in[4];
    const float* Wk    = (const float*)d_in[5];
    const float* bk    = (const float*)d_in[6];
    const float* Wv    = (const float*)d_in[7];
    const float* bv    = (const float*)d_in[8];
    const float* Wo    = (const float*)d_in[9];
    const float* bo    = (const float*)d_in[10];
    const float* Aq    = (const float*)d_in[11];
    const float* Ak    = (const float*)d_in[12];
    const float* av    = (const float*)d_in[13];
    float* out = (float*)d_out;

    float *pWqE, *pWkE, *pbqE, *pbkE, *pqp, *pkp, *pV, *patt;
    cudaGetSymbolAddress((void**)&pWqE, g_WqE);
    cudaGetSymbolAddress((void**)&pWkE, g_WkE);
    cudaGetSymbolAddress((void**)&pbqE, g_bqE);
    cudaGetSymbolAddress((void**)&pbkE, g_bkE);
    cudaGetSymbolAddress((void**)&pqp,  g_qp);
    cudaGetSymbolAddress((void**)&pkp,  g_kp);
    cudaGetSymbolAddress((void**)&pV,   g_V);
    cudaGetSymbolAddress((void**)&patt, g_att);

    cudaFuncSetAttribute(attn_kernel, cudaFuncAttributeMaxDynamicSharedMemorySize, ATTN_SMEM);

    // prep: effective Q/K weights + biases (coalesced mini-GEMMs)
    prep_eff<<<dim3(8, 8, 2), 256>>>(Wq, Aq, Wk, Ak, bq, bk);

    // fused Q/K/V projection GEMMs (Wv consumed raw via transposed-B path)
    dim3 gg(DMODEL/64, BL/64, 3);
    gemm_v3<<<gg, 256>>>(query, pWqE, pbqE, pqp, 0,
                         key,   pWkE, pbkE, pkp, 0,
                         value, Wv,   bv,   pV,  1);

    attn_kernel<<<dim3(SEQ/32, BATCH*NHEADS), 256, ATTN_SMEM>>>(pqp, pkp, pV, av, patt);

    // output projection (Wo raw, transposed-B path)
    dim3 go(DMODEL/64, BL/64, 1);
    gemm_v3<<<go, 256>>>(patt, Wo, bo, out, 1,
                         nullptr, nullptr, nullptr, nullptr, 0,
                         nullptr, nullptr, nullptr, nullptr, 0);
}

// round 8
// speedup vs baseline: 1.9824x; 1.0683x over previous
#include <cuda_runtime.h>
#include <cuda_bf16.h>

// Problem constants (fixed by reference)
#define BATCH   2
#define SEQ     512
#define DMODEL  512
#define NHEADS  8
#define DK      64
#define BL      (BATCH*SEQ)   // 1024 rows
#define HALF    (BL*DMODEL)   // one partial buffer (floats)

// ---------------- scratch (device globals; no allocation allowed) ----------
__device__ float g_WqE[DMODEL*DMODEL];
__device__ float g_WkE[DMODEL*DMODEL];
__device__ float g_bqE[DMODEL];
__device__ float g_bkE[DMODEL];
__device__ float g_qp[2*HALF];   // [0]: k-half partial 0 (then reduced in place)
__device__ float g_kp[2*HALF];
__device__ float g_V [2*HALF];
__device__ float g_att[HALF];
__device__ float g_wp[4*HALF];   // Wo split-K partials

__device__ __forceinline__ float tanh_fast(float x) {
    float y;
    asm("tanh.approx.f32 %0, %1;" : "=f"(y) : "f"(x));
    return y;
}

// ---------------------------------------------------------------------------
// Prep: effective weights via tiled mini-GEMMs (coalesced).
//   WE[i][h*64+dp] = sum_d W[(h*64+d)*512 + i] * A[dp*64 + d]
//   bE[h*64+dp]    = sum_d b[h*64+d] * A[dp*64+d]
// grid (8 i-tiles, 8 heads, 2 q/k), 256 threads.
// ---------------------------------------------------------------------------
__global__ __launch_bounds__(256) void prep_eff(
    const float* __restrict__ Wq, const float* __restrict__ Aq,
    const float* __restrict__ Wk, const float* __restrict__ Ak,
    const float* __restrict__ bq, const float* __restrict__ bk) {
    __shared__ float Ws[64*68];   // Ws[d][ii]
    __shared__ float At[64*68];   // At[d][dp]
    int t   = threadIdx.x;
    int it  = blockIdx.x;
    int h   = blockIdx.y;
    int sel = blockIdx.z;
    const float* W = sel ? Wk : Wq;
    const float* A = sel ? Ak : Aq;
    float* WE = sel ? g_WkE : g_WqE;
    const float* bsrc = sel ? bk : bq;
    float* bE = sel ? g_bkE : g_bqE;

    for (int idx = t; idx < 64*64; idx += 256) {
        int d = idx >> 6, ii = idx & 63;
        Ws[d*68 + ii] = W[(h*64 + d)*DMODEL + it*64 + ii];
    }
    for (int idx = t; idx < 64*64; idx += 256) {
        int dp = idx >> 6, d = idx & 63;
        At[d*68 + dp] = A[dp*64 + d];
    }
    __syncthreads();

    int tx = t & 15, ty = t >> 4;
    int dp4 = tx * 4, ii4 = ty * 4;
    float acc[4][4];
#pragma unroll
    for (int i = 0; i < 4; i++)
#pragma unroll
        for (int j = 0; j < 4; j++) acc[i][j] = 0.f;

#pragma unroll 8
    for (int d = 0; d < 64; d++) {
        float4 a4 = *(const float4*)&Ws[d*68 + ii4];
        float4 b4 = *(const float4*)&At[d*68 + dp4];
        float aa[4] = {a4.x, a4.y, a4.z, a4.w};
        float bb[4] = {b4.x, b4.y, b4.z, b4.w};
#pragma unroll
        for (int i = 0; i < 4; i++)
#pragma unroll
            for (int j = 0; j < 4; j++)
                acc[i][j] += aa[i] * bb[j];
    }
#pragma unroll
    for (int i = 0; i < 4; i++) {
        int row = it*64 + ii4 + i;
        *(float4*)&WE[row*DMODEL + h*64 + dp4] =
            make_float4(acc[i][0], acc[i][1], acc[i][2], acc[i][3]);
    }
    if (it == 0 && t < 64) {
        float s = 0.f;
#pragma unroll 8
        for (int d = 0; d < 64; d++)
            s += bsrc[h*64 + d] * At[d*68 + t];
        bE[h*64 + t] = s;
    }
}

// ---------------------------------------------------------------------------
// GEMM v4 (split-K): Cpart = A[:, k0:k0+KS] @ B-slice. M=1024, N=K=512.
// 128x64 tile, 256 threads, 8x4 microtile, double-buffered, 1 sync/k-tile.
// tb: 0 -> B is [K][N];  1 -> B is [N][K] (read transposed on the fly).
// blockIdx.z: g = z/nsplit selects GEMM, part = z%nsplit selects K slice.
// Partial (no bias) written to C_g + part*HALF.
// ---------------------------------------------------------------------------
__global__ __launch_bounds__(256) void gemm_v4(
    const float* __restrict__ A0, const float* __restrict__ B0, int t0, float* __restrict__ C0,
    const float* __restrict__ A1, const float* __restrict__ B1, int t1, float* __restrict__ C1,
    const float* __restrict__ A2, const float* __restrict__ B2, int t2, float* __restrict__ C2,
    int nsplit, int KS) {
    const int K = DMODEL, N = DMODEL;
    int z = blockIdx.z;
    int g = z / nsplit, part = z - g * nsplit;
    const float* A  = (g == 0) ? A0 : (g == 1) ? A1 : A2;
    const float* Bm = (g == 0) ? B0 : (g == 1) ? B1 : B2;
    int tb          = (g == 0) ? t0 : (g == 1) ? t1 : t2;
    float* C        = ((g == 0) ? C0 : (g == 1) ? C1 : C2) + part * HALF;
    int kbase = part * KS;

    __shared__ float As[2][16*132];
    __shared__ float Bs[2][16*68];

    int t  = threadIdx.x;          // 256
    int bm = blockIdx.y * 128;
    int bn = blockIdx.x * 64;
    int tx = t & 15, ty = t >> 4;  // tx: 16 (N x4), ty: 16 (M x8)

    float acc[8][4];
#pragma unroll
    for (int i = 0; i < 8; i++)
#pragma unroll
        for (int j = 0; j < 4; j++) acc[i][j] = 0.f;

    int ar0 = t >> 2, akc = (t & 3) << 2;     // A chunk coords (row 0..63)
    int bkr = t >> 4, bnc = (t & 15) << 2;    // B coords (tb=0)

    float4 ra0, ra1, rb;
    auto fetch = [&](int k0) {
        ra0 = *(const float4*)(A + (bm +      ar0)*K + k0 + akc);
        ra1 = *(const float4*)(A + (bm + 64 + ar0)*K + k0 + akc);
        if (tb == 0)
            rb = *(const float4*)(Bm + (k0 + bkr)*N + bn + bnc);
        else
            rb = *(const float4*)(Bm + (bn + ar0)*K + k0 + akc);
    };
    auto stage = [&](int buf) {
        As[buf][(akc+0)*132 + ar0] = ra0.x;
        As[buf][(akc+1)*132 + ar0] = ra0.y;
        As[buf][(akc+2)*132 + ar0] = ra0.z;
        As[buf][(akc+3)*132 + ar0] = ra0.w;
        As[buf][(akc+0)*132 + 64 + ar0] = ra1.x;
        As[buf][(akc+1)*132 + 64 + ar0] = ra1.y;
        As[buf][(akc+2)*132 + 64 + ar0] = ra1.z;
        As[buf][(akc+3)*132 + 64 + ar0] = ra1.w;
        if (tb == 0) {
            *(float4*)&Bs[buf][bkr*68 + bnc] = rb;
        } else {
            Bs[buf][(akc+0)*68 + ar0] = rb.x;
            Bs[buf][(akc+1)*68 + ar0] = rb.y;
            Bs[buf][(akc+2)*68 + ar0] = rb.z;
            Bs[buf][(akc+3)*68 + ar0] = rb.w;
        }
    };

    fetch(kbase);
    stage(0);
    int cur = 0;
    int kend = kbase + KS;
    for (int k0 = kbase; k0 < kend; k0 += 16) {
        __syncthreads();
        bool more = (k0 + 16) < kend;
        if (more) fetch(k0 + 16);
#pragma unroll
        for (int k = 0; k < 16; k++) {
            float4 aA = *(const float4*)&As[cur][k*132 + ty*8];
            float4 aB = *(const float4*)&As[cur][k*132 + ty*8 + 4];
            float4 b4 = *(const float4*)&Bs[cur][k*68 + tx*4];
            float am[8] = {aA.x, aA.y, aA.z, aA.w, aB.x, aB.y, aB.z, aB.w};
            float bb[4] = {b4.x, b4.y, b4.z, b4.w};
#pragma unroll
            for (int i = 0; i < 8; i++)
#pragma unroll
                for (int j = 0; j < 4; j++)
                    acc[i][j] += am[i] * bb[j];
        }
        if (more) stage(cur ^ 1);
        cur ^= 1;
    }

#pragma unroll
    for (int i = 0; i < 8; i++) {
        int row = bm + ty*8 + i;
        *(float4*)&C[row*N + bn + tx*4] =
            make_float4(acc[i][0], acc[i][1], acc[i][2], acc[i][3]);
    }
}

// ---------------------------------------------------------------------------
// Reduce QKV partials in place: P[f] = P[f] + P[f+HALF] + bias[col]
// ---------------------------------------------------------------------------
__global__ __launch_bounds__(256) void reduce_qkv(
    const float* __restrict__ bv) {
    int idx = blockIdx.x * blockDim.x + threadIdx.x;   // 0 .. 3*131072-1
    int sel = idx / (HALF/4);
    int f   = idx - sel * (HALF/4);
    float* P = (sel == 0) ? g_qp : (sel == 1) ? g_kp : g_V;
    const float* bias = (sel == 0) ? g_bqE : (sel == 1) ? g_bkE : bv;
    float4 x = *(const float4*)(P + f*4);
    float4 y = *(const float4*)(P + HALF + f*4);
    float4 b = *(const float4*)(bias + (f & 127)*4);
    x.x += y.x + b.x; x.y += y.y + b.y;
    x.z += y.z + b.z; x.w += y.w + b.w;
    *(float4*)(P + f*4) = x;
}

// ---------------------------------------------------------------------------
// Reduce Wo partials: out = wp0+wp1+wp2+wp3 + bo
// ---------------------------------------------------------------------------
__global__ __launch_bounds__(256) void reduce_out(
    float* __restrict__ out, const float* __restrict__ bo) {
    int f = blockIdx.x * blockDim.x + threadIdx.x;     // 0 .. 131071
    float4 a = *(const float4*)(g_wp + f*4);
    float4 b = *(const float4*)(g_wp + HALF + f*4);
    float4 c = *(const float4*)(g_wp + 2*HALF + f*4);
    float4 d = *(const float4*)(g_wp + 3*HALF + f*4);
    float4 bb = *(const float4*)(bo + (f & 127)*4);
    float4 o;
    o.x = a.x + b.x + c.x + d.x + bb.x;
    o.y = a.y + b.y + c.y + d.y + bb.y;
    o.z = a.z + b.z + c.z + d.z + bb.z;
    o.w = a.w + b.w + c.w + d.w + bb.w;
    *(float4*)(out + f*4) = o;
}

// ---------------------------------------------------------------------------
// Attention (f32 tanh.approx, prefetched tiles) — unchanged from R7-passing.
// ---------------------------------------------------------------------------
#define SK_LD 68
#define SC_LD 513
#define ATTN_SMEM ((64*SK_LD + 32*SC_LD + 64 + 32) * 4)

__global__ __launch_bounds__(256) void attn_kernel(
    const float* __restrict__ qp, const float* __restrict__ kp,
    const float* __restrict__ V,  const float* __restrict__ av,
    float* __restrict__ out) {
    extern __shared__ float sm[];
    float* sk      = sm;                     // 64 x 68 (kp then V tiles)
    float* sc      = sm + 64*SK_LD;          // 32 x 513
    float* s_av    = sc + 32*SC_LD;          // 64
    float* s_scale = s_av + 64;              // 32

    int t    = threadIdx.x;                  // 256
    int lane = t & 31;
    int wid  = t >> 5;
    int i0   = blockIdx.x * 32;
    int bh   = blockIdx.y;
    int b    = bh >> 3, h = bh & 7;
    const int h64 = h * 64;
    const int rowbase = b * SEQ;

    if (t < 64) s_av[t] = av[t];

    float q_r[64];
    {
        const float* qrow = qp + (rowbase + i0 + lane) * DMODEL + h64;
#pragma unroll
        for (int d = 0; d < 64; d += 4) {
            float4 v4 = *(const float4*)(qrow + d);
            q_r[d] = v4.x; q_r[d+1] = v4.y; q_r[d+2] = v4.z; q_r[d+3] = v4.w;
        }
    }
    __syncthreads();

    int frow = t >> 2;
    int fc16 = (t & 3) << 4;
    float4 f0, f1, f2, f3;
    auto fetchT = [&](const float* base, int jt) {
        const float* src = base + (rowbase + jt + frow) * DMODEL + h64 + fc16;
        f0 = *(const float4*)(src + 0);
        f1 = *(const float4*)(src + 4);
        f2 = *(const float4*)(src + 8);
        f3 = *(const float4*)(src + 12);
    };
    auto stageT = [&]() {
        float* dst = &sk[frow*SK_LD + fc16];
        *(float4*)(dst + 0)  = f0;
        *(float4*)(dst + 4)  = f1;
        *(float4*)(dst + 8)  = f2;
        *(float4*)(dst + 12) = f3;
    };

    // ---- phase 1: scores (MUFU-bound, f32 tanh) ----
    fetchT(kp, 0);
    for (int jt = 0; jt < SEQ; jt += 64) {
        stageT();
        __syncthreads();
        if (jt + 64 < SEQ) fetchT(kp, jt + 64);
#pragma unroll
        for (int jj = 0; jj < 8; jj++) {
            int j = wid * 8 + jj;
            const float* krow = &sk[j*SK_LD];
            float s = 0.f;
#pragma unroll
            for (int d = 0; d < 64; d += 4) {
                float4 k4 = *(const float4*)(krow + d);
                float4 a4 = *(const float4*)(&s_av[d]);
                s += a4.x * tanh_fast(q_r[d+0] + k4.x);
                s += a4.y * tanh_fast(q_r[d+1] + k4.y);
                s += a4.z * tanh_fast(q_r[d+2] + k4.z);
                s += a4.w * tanh_fast(q_r[d+3] + k4.w);
            }
            sc[lane*SC_LD + jt + j] = s;
        }
        __syncthreads();
    }

    // ---- phase 2: softmax ----
#pragma unroll
    for (int r = 0; r < 4; r++) {
        int ri = wid * 4 + r;
        float m = -1e30f;
        for (int c = lane; c < SEQ; c += 32)
            m = fmaxf(m, sc[ri*SC_LD + c]);
#pragma unroll
        for (int o = 16; o; o >>= 1) m = fmaxf(m, __shfl_xor_sync(~0u, m, o));
        float sum = 0.f;
        for (int c = lane; c < SEQ; c += 32) {
            float p = __expf(sc[ri*SC_LD + c] - m);
            sc[ri*SC_LD + c] = p;
            sum += p;
        }
#pragma unroll
        for (int o = 16; o; o >>= 1) sum += __shfl_xor_sync(~0u, sum, o);
        if (lane == 0) s_scale[ri] = 1.f / sum;
    }
    __syncthreads();

    // ---- phase 3: out = P @ V ----
    int dt = t & 15, ig = t >> 4;
    int d4 = dt << 2;
    int ia = ig << 1;
    float acc0[4] = {0.f, 0.f, 0.f, 0.f};
    float acc1[4] = {0.f, 0.f, 0.f, 0.f};

    fetchT(V, 0);
    for (int jt = 0; jt < SEQ; jt += 64) {
        stageT();
        __syncthreads();
        if (jt + 64 < SEQ) fetchT(V, jt + 64);
        const float* p0 = &sc[ia*SC_LD + jt];
        const float* p1 = &sc[(ia+1)*SC_LD + jt];
#pragma unroll 8
        for (int j = 0; j < 64; j++) {
            float4 v = *(const float4*)&sk[j*SK_LD + d4];
            float pa = p0[j];
            float pb = p1[j];
            acc0[0] += pa * v.x; acc0[1] += pa * v.y;
            acc0[2] += pa * v.z; acc0[3] += pa * v.w;
            acc1[0] += pb * v.x; acc1[1] += pb * v.y;
            acc1[2] += pb * v.z; acc1[3] += pb * v.w;
        }
        __syncthreads();
    }
    float s0 = s_scale[ia], s1 = s_scale[ia+1];
    float4 o0, o1;
    o0.x = acc0[0]*s0; o0.y = acc0[1]*s0; o0.z = acc0[2]*s0; o0.w = acc0[3]*s0;
    o1.x = acc1[0]*s1; o1.y = acc1[1]*s1; o1.z = acc1[2]*s1; o1.w = acc1[3]*s1;
    *(float4*)&out[(rowbase + i0 + ia    ) * DMODEL + h64 + d4] = o0;
    *(float4*)&out[(rowbase + i0 + ia + 1) * DMODEL + h64 + d4] = o1;
}

// ---------------------------------------------------------------------------
extern "C" void kernel_launch(void* const* d_in, const int* in_sizes, int n_in,
                              void* d_out, int out_size) {
    const float* query = (const float*)d_in[0];
    const float* key   = (const float*)d_in[1];
    const float* value = (const float*)d_in[2];
    const float* Wq    = (const float*)d_in[3];
    const float* bq    = (const float*)d_in[4];
    const float* Wk    = (const float*)d_in[5];
    const float* bk    = (const float*)d_in[6];
    const float* Wv    = (const float*)d_in[7];
    const float* bv    = (const float*)d_in[8];
    const float* Wo    = (const float*)d_in[9];
    const float* bo    = (const float*)d_in[10];
    const float* Aq    = (const float*)d_in[11];
    const float* Ak    = (const float*)d_in[12];
    const float* av    = (const float*)d_in[13];
    float* out = (float*)d_out;

    float *pWqE, *pWkE, *pqp, *pkp, *pV, *patt, *pwp;
    cudaGetSymbolAddress((void**)&pWqE, g_WqE);
    cudaGetSymbolAddress((void**)&pWkE, g_WkE);
    cudaGetSymbolAddress((void**)&pqp,  g_qp);
    cudaGetSymbolAddress((void**)&pkp,  g_kp);
    cudaGetSymbolAddress((void**)&pV,   g_V);
    cudaGetSymbolAddress((void**)&patt, g_att);
    cudaGetSymbolAddress((void**)&pwp,  g_wp);

    cudaFuncSetAttribute(attn_kernel, cudaFuncAttributeMaxDynamicSharedMemorySize, ATTN_SMEM);

    // prep: effective Q/K weights + biases
    prep_eff<<<dim3(8, 8, 2), 256>>>(Wq, Aq, Wk, Ak, bq, bk);

    // Q/K/V projection GEMMs, split-K x2 (6 slices), 128x64 tiles -> 384 CTAs
    gemm_v4<<<dim3(8, 8, 6), 256>>>(query, pWqE, 0, pqp,
                                    key,   pWkE, 0, pkp,
                                    value, Wv,   1, pV,
                                    2, 256);
    // fold partials + biases in place
    reduce_qkv<<<(3*(HALF/4) + 255)/256, 256>>>(bv);

    attn_kernel<<<dim3(SEQ/32, BATCH*NHEADS), 256, ATTN_SMEM>>>(pqp, pkp, pV, av, patt);

    // output projection, split-K x4 -> 256 CTAs
    gemm_v4<<<dim3(8, 8, 4), 256>>>(patt, Wo, 1, pwp,
                                    patt, Wo, 1, pwp,
                                    patt, Wo, 1, pwp,
                                    4, 128);
    reduce_out<<<(HALF/4)/256, 256>>>(out, bo);
}

// round 11
// speedup vs baseline: 2.0210x; 1.0195x over previous
#include <cuda_runtime.h>
#include <cuda_bf16.h>

// Problem constants (fixed by reference)
#define BATCH   2
#define SEQ     512
#define DMODEL  512
#define NHEADS  8
#define DK      64
#define BL      (BATCH*SEQ)   // 1024 rows
#define HALF    (BL*DMODEL)   // one partial buffer (floats)

// ---------------- scratch (device globals; no allocation allowed) ----------
__device__ float g_WqE[DMODEL*DMODEL];
__device__ float g_WkE[DMODEL*DMODEL];
__device__ float g_bqE[DMODEL];
__device__ float g_bkE[DMODEL];
__device__ float g_qp[2*HALF];   // partial 0/1, reduced in place
__device__ float g_kp[2*HALF];
__device__ float g_V [2*HALF];
__device__ float g_att[HALF];
__device__ float g_wp[4*HALF];   // Wo split-K partials

__device__ __forceinline__ float tanh_fast(float x) {
    float y;
    asm("tanh.approx.f32 %0, %1;" : "=f"(y) : "f"(x));
    return y;
}

// ---------------------------------------------------------------------------
// Prep: effective weights via tiled mini-GEMMs (coalesced).
// ---------------------------------------------------------------------------
__global__ __launch_bounds__(256) void prep_eff(
    const float* __restrict__ Wq, const float* __restrict__ Aq,
    const float* __restrict__ Wk, const float* __restrict__ Ak,
    const float* __restrict__ bq, const float* __restrict__ bk) {
    __shared__ float Ws[64*68];   // Ws[d][ii]
    __shared__ float At[64*68];   // At[d][dp]
    int t   = threadIdx.x;
    int it  = blockIdx.x;
    int h   = blockIdx.y;
    int sel = blockIdx.z;
    const float* W = sel ? Wk : Wq;
    const float* A = sel ? Ak : Aq;
    float* WE = sel ? g_WkE : g_WqE;
    const float* bsrc = sel ? bk : bq;
    float* bE = sel ? g_bkE : g_bqE;

    for (int idx = t; idx < 64*64; idx += 256) {
        int d = idx >> 6, ii = idx & 63;
        Ws[d*68 + ii] = W[(h*64 + d)*DMODEL + it*64 + ii];
    }
    for (int idx = t; idx < 64*64; idx += 256) {
        int dp = idx >> 6, d = idx & 63;
        At[d*68 + dp] = A[dp*64 + d];
    }
    __syncthreads();

    int tx = t & 15, ty = t >> 4;
    int dp4 = tx * 4, ii4 = ty * 4;
    float acc[4][4];
#pragma unroll
    for (int i = 0; i < 4; i++)
#pragma unroll
        for (int j = 0; j < 4; j++) acc[i][j] = 0.f;

#pragma unroll 8
    for (int d = 0; d < 64; d++) {
        float4 a4 = *(const float4*)&Ws[d*68 + ii4];
        float4 b4 = *(const float4*)&At[d*68 + dp4];
        float aa[4] = {a4.x, a4.y, a4.z, a4.w};
        float bb[4] = {b4.x, b4.y, b4.z, b4.w};
#pragma unroll
        for (int i = 0; i < 4; i++)
#pragma unroll
            for (int j = 0; j < 4; j++)
                acc[i][j] += aa[i] * bb[j];
    }
#pragma unroll
    for (int i = 0; i < 4; i++) {
        int row = it*64 + ii4 + i;
        *(float4*)&WE[row*DMODEL + h*64 + dp4] =
            make_float4(acc[i][0], acc[i][1], acc[i][2], acc[i][3]);
    }
    if (it == 0 && t < 64) {
        float s = 0.f;
#pragma unroll 8
        for (int d = 0; d < 64; d++)
            s += bsrc[h*64 + d] * At[d*68 + t];
        bE[h*64 + t] = s;
    }
}

// ---------------------------------------------------------------------------
// GEMM v4 (split-K): Cpart = A[:, slice] @ B-slice. M=1024, N=K=512.
// 128x64 tile, 256 threads, 8x4 microtile, double-buffered, 1 sync/k-tile.
// ---------------------------------------------------------------------------
__global__ __launch_bounds__(256) void gemm_v4(
    const float* __restrict__ A0, const float* __restrict__ B0, int t0, float* __restrict__ C0,
    const float* __restrict__ A1, const float* __restrict__ B1, int t1, float* __restrict__ C1,
    const float* __restrict__ A2, const float* __restrict__ B2, int t2, float* __restrict__ C2,
    int nsplit, int KS) {
    const int K = DMODEL, N = DMODEL;
    int z = blockIdx.z;
    int g = z / nsplit, part = z - g * nsplit;
    const float* A  = (g == 0) ? A0 : (g == 1) ? A1 : A2;
    const float* Bm = (g == 0) ? B0 : (g == 1) ? B1 : B2;
    int tb          = (g == 0) ? t0 : (g == 1) ? t1 : t2;
    float* C        = ((g == 0) ? C0 : (g == 1) ? C1 : C2) + part * HALF;
    int kbase = part * KS;

    __shared__ float As[2][16*132];
    __shared__ float Bs[2][16*68];

    int t  = threadIdx.x;          // 256
    int bm = blockIdx.y * 128;
    int bn = blockIdx.x * 64;
    int tx = t & 15, ty = t >> 4;

    float acc[8][4];
#pragma unroll
    for (int i = 0; i < 8; i++)
#pragma unroll
        for (int j = 0; j < 4; j++) acc[i][j] = 0.f;

    int ar0 = t >> 2, akc = (t & 3) << 2;
    int bkr = t >> 4, bnc = (t & 15) << 2;

    float4 ra0, ra1, rb;
    auto fetch = [&](int k0) {
        ra0 = *(const float4*)(A + (bm +      ar0)*K + k0 + akc);
        ra1 = *(const float4*)(A + (bm + 64 + ar0)*K + k0 + akc);
        if (tb == 0)
            rb = *(const float4*)(Bm + (k0 + bkr)*N + bn + bnc);
        else
            rb = *(const float4*)(Bm + (bn + ar0)*K + k0 + akc);
    };
    auto stage = [&](int buf) {
        As[buf][(akc+0)*132 + ar0] = ra0.x;
        As[buf][(akc+1)*132 + ar0] = ra0.y;
        As[buf][(akc+2)*132 + ar0] = ra0.z;
        As[buf][(akc+3)*132 + ar0] = ra0.w;
        As[buf][(akc+0)*132 + 64 + ar0] = ra1.x;
        As[buf][(akc+1)*132 + 64 + ar0] = ra1.y;
        As[buf][(akc+2)*132 + 64 + ar0] = ra1.z;
        As[buf][(akc+3)*132 + 64 + ar0] = ra1.w;
        if (tb == 0) {
            *(float4*)&Bs[buf][bkr*68 + bnc] = rb;
        } else {
            Bs[buf][(akc+0)*68 + ar0] = rb.x;
            Bs[buf][(akc+1)*68 + ar0] = rb.y;
            Bs[buf][(akc+2)*68 + ar0] = rb.z;
            Bs[buf][(akc+3)*68 + ar0] = rb.w;
        }
    };

    fetch(kbase);
    stage(0);
    int cur = 0;
    int kend = kbase + KS;
    for (int k0 = kbase; k0 < kend; k0 += 16) {
        __syncthreads();
        bool more = (k0 + 16) < kend;
        if (more) fetch(k0 + 16);
#pragma unroll
        for (int k = 0; k < 16; k++) {
            float4 aA = *(const float4*)&As[cur][k*132 + ty*8];
            float4 aB = *(const float4*)&As[cur][k*132 + ty*8 + 4];
            float4 b4 = *(const float4*)&Bs[cur][k*68 + tx*4];
            float am[8] = {aA.x, aA.y, aA.z, aA.w, aB.x, aB.y, aB.z, aB.w};
            float bb[4] = {b4.x, b4.y, b4.z, b4.w};
#pragma unroll
            for (int i = 0; i < 8; i++)
#pragma unroll
                for (int j = 0; j < 4; j++)
                    acc[i][j] += am[i] * bb[j];
        }
        if (more) stage(cur ^ 1);
        cur ^= 1;
    }

#pragma unroll
    for (int i = 0; i < 8; i++) {
        int row = bm + ty*8 + i;
        *(float4*)&C[row*N + bn + tx*4] =
            make_float4(acc[i][0], acc[i][1], acc[i][2], acc[i][3]);
    }
}

// ---------------------------------------------------------------------------
// Reduce QKV partials in place: P[f] = P[f] + P[f+HALF] + bias[col]
// ---------------------------------------------------------------------------
__global__ __launch_bounds__(256) void reduce_qkv(
    const float* __restrict__ bv) {
    int idx = blockIdx.x * blockDim.x + threadIdx.x;
    int sel = idx / (HALF/4);
    int f   = idx - sel * (HALF/4);
    float* P = (sel == 0) ? g_qp : (sel == 1) ? g_kp : g_V;
    const float* bias = (sel == 0) ? g_bqE : (sel == 1) ? g_bkE : bv;
    float4 x = *(const float4*)(P + f*4);
    float4 y = *(const float4*)(P + HALF + f*4);
    float4 b = *(const float4*)(bias + (f & 127)*4);
    x.x += y.x + b.x; x.y += y.y + b.y;
    x.z += y.z + b.z; x.w += y.w + b.w;
    *(float4*)(P + f*4) = x;
}

// ---------------------------------------------------------------------------
// Reduce Wo partials: out = wp0+wp1+wp2+wp3 + bo
// ---------------------------------------------------------------------------
__global__ __launch_bounds__(256) void reduce_out(
    float* __restrict__ out, const float* __restrict__ bo) {
    int f = blockIdx.x * blockDim.x + threadIdx.x;
    float4 a = *(const float4*)(g_wp + f*4);
    float4 b = *(const float4*)(g_wp + HALF + f*4);
    float4 c = *(const float4*)(g_wp + 2*HALF + f*4);
    float4 d = *(const float4*)(g_wp + 3*HALF + f*4);
    float4 bb = *(const float4*)(bo + (f & 127)*4);
    float4 o;
    o.x = a.x + b.x + c.x + d.x + bb.x;
    o.y = a.y + b.y + c.y + d.y + bb.y;
    o.z = a.z + b.z + c.z + d.z + bb.z;
    o.w = a.w + b.w + c.w + d.w + bb.w;
    *(float4*)(out + f*4) = o;
}

// ---------------------------------------------------------------------------
// Attention v2 — fused streaming softmax (no max subtraction; scores are
// bounded by sum|av| <~ 10, so exp can't overflow in f32).
// Per 64-j tile: stage K+V -> phase A (tanh scores -> p=exp(s) -> P-tile smem,
// running per-query sum in regs) -> phase B (acc += P @ V) -> next tile.
// Final: scale acc by 1/sum. MUFU (A) and FMA/LDS (B) interleave per tile.
// ---------------------------------------------------------------------------
__global__ __launch_bounds__(256, 2) void attn_kernel(
    const float* __restrict__ qp, const float* __restrict__ kp,
    const float* __restrict__ V,  const float* __restrict__ av,
    float* __restrict__ out) {
    __shared__ float sk[64*68];     // K tile
    __shared__ float sv[64*68];     // V tile
    __shared__ float sp[32*65];     // P tile (32 queries x 64 j, pad 65)
    __shared__ float s_av[64];
    __shared__ float s_part[8*32];  // per-warp partial softmax sums
    __shared__ float s_inv[32];

    int t    = threadIdx.x;         // 256
    int lane = t & 31;
    int wid  = t >> 5;
    int i0   = blockIdx.x * 32;
    int bh   = blockIdx.y;
    int b    = bh >> 3, h = bh & 7;
    const int h64 = h * 64;
    const int rowbase = b * SEQ;

    if (t < 64) s_av[t] = av[t];

    // cache this thread's query row (query = lane) in registers
    float q_r[64];
    {
        const float* qrow = qp + (rowbase + i0 + lane) * DMODEL + h64;
#pragma unroll
        for (int d = 0; d < 64; d += 4) {
            float4 v4 = *(const float4*)(qrow + d);
            q_r[d] = v4.x; q_r[d+1] = v4.y; q_r[d+2] = v4.z; q_r[d+3] = v4.w;
        }
    }

    // phase-B mapping: thread owns 2 queries x 4 d
    int dt = t & 15, ig = t >> 4;
    int d4 = dt << 2;
    int ia = ig << 1;
    float acc0[4] = {0.f, 0.f, 0.f, 0.f};
    float acc1[4] = {0.f, 0.f, 0.f, 0.f};
    float psum = 0.f;               // partial sum of exp over this thread's j's

    // tile staging coords: row = t>>2, 16-float chunk = (t&3)*16
    int frow = t >> 2;
    int fc16 = (t & 3) << 4;

    __syncthreads();                // s_av visible

    for (int jt = 0; jt < SEQ; jt += 64) {
        // ---- stage K and V tiles (8 LDG.128 in flight) ----
        {
            const float* ks = kp + (rowbase + jt + frow) * DMODEL + h64 + fc16;
            const float* vs = V  + (rowbase + jt + frow) * DMODEL + h64 + fc16;
            float4 k0 = *(const float4*)(ks + 0);
            float4 k1 = *(const float4*)(ks + 4);
            float4 k2 = *(const float4*)(ks + 8);
            float4 k3 = *(const float4*)(ks + 12);
            float4 v0 = *(const float4*)(vs + 0);
            float4 v1 = *(const float4*)(vs + 4);
            float4 v2 = *(const float4*)(vs + 8);
            float4 v3 = *(const float4*)(vs + 12);
            float* dk = &sk[frow*68 + fc16];
            float* dv = &sv[frow*68 + fc16];
            *(float4*)(dk + 0)  = k0;
            *(float4*)(dk + 4)  = k1;
            *(float4*)(dk + 8)  = k2;
            *(float4*)(dk + 12) = k3;
            *(float4*)(dv + 0)  = v0;
            *(float4*)(dv + 4)  = v1;
            *(float4*)(dv + 8)  = v2;
            *(float4*)(dv + 12) = v3;
        }
        __syncthreads();

        // ---- phase A: scores -> p = exp(s) -> P tile ----
#pragma unroll
        for (int jj = 0; jj < 8; jj++) {
            int j = wid * 8 + jj;            // warp-uniform -> broadcast LDS
            const float* krow = &sk[j*68];
            float s = 0.f;
#pragma unroll
            for (int d = 0; d < 64; d += 4) {
                float4 k4 = *(const float4*)(krow + d);
                float4 a4 = *(const float4*)(&s_av[d]);
                s += a4.x * tanh_fast(q_r[d+0] + k4.x);
                s += a4.y * tanh_fast(q_r[d+1] + k4.y);
                s += a4.z * tanh_fast(q_r[d+2] + k4.z);
                s += a4.w * tanh_fast(q_r[d+3] + k4.w);
            }
            float p = __expf(s);             // |s| <= sum|av| ~ 10: safe
            sp[lane*65 + j] = p;
            psum += p;
        }
        __syncthreads();

        // ---- phase B: acc += P @ V ----
        const float* p0 = &sp[ia*65];
        const float* p1 = &sp[(ia+1)*65];
#pragma unroll 8
        for (int j = 0; j < 64; j++) {
            float4 v = *(const float4*)&sv[j*68 + d4];
            float pa = p0[j];
            float pb = p1[j];
            acc0[0] += pa * v.x; acc0[1] += pa * v.y;
            acc0[2] += pa * v.z; acc0[3] += pa * v.w;
            acc1[0] += pb * v.x; acc1[1] += pb * v.y;
            acc1[2] += pb * v.z; acc1[3] += pb * v.w;
        }
        __syncthreads();                     // safe to restage sk/sv/sp
    }

    // ---- finalize softmax sums ----
    s_part[wid*32 + lane] = psum;            // psum covers this thread's j's
    __syncthreads();
    if (t < 32) {
        float ssum = 0.f;
#pragma unroll
        for (int w = 0; w < 8; w++) ssum += s_part[w*32 + t];
        s_inv[t] = 1.f / ssum;
    }
    __syncthreads();

    float s0 = s_inv[ia], s1 = s_inv[ia+1];
    float4 o0, o1;
    o0.x = acc0[0]*s0; o0.y = acc0[1]*s0; o0.z = acc0[2]*s0; o0.w = acc0[3]*s0;
    o1.x = acc1[0]*s1; o1.y = acc1[1]*s1; o1.z = acc1[2]*s1; o1.w = acc1[3]*s1;
    *(float4*)&out[(rowbase + i0 + ia    ) * DMODEL + h64 + d4] = o0;
    *(float4*)&out[(rowbase + i0 + ia + 1) * DMODEL + h64 + d4] = o1;
}

// ---------------------------------------------------------------------------
extern "C" void kernel_launch(void* const* d_in, const int* in_sizes, int n_in,
                              void* d_out, int out_size) {
    const float* query = (const float*)d_in[0];
    const float* key   = (const float*)d_in[1];
    const float* value = (const float*)d_in[2];
    const float* Wq    = (const float*)d_in[3];
    const float* bq    = (const float*)d_in[4];
    const float* Wk    = (const float*)d_in[5];
    const float* bk    = (const float*)d_in[6];
    const float* Wv    = (const float*)d_in[7];
    const float* bv    = (const float*)d_in[8];
    const float* Wo    = (const float*)d_in[9];
    const float* bo    = (const float*)d_in[10];
    const float* Aq    = (const float*)d_in[11];
    const float* Ak    = (const float*)d_in[12];
    const float* av    = (const float*)d_in[13];
    float* out = (float*)d_out;

    float *pWqE, *pWkE, *pqp, *pkp, *pV, *patt, *pwp;
    cudaGetSymbolAddress((void**)&pWqE, g_WqE);
    cudaGetSymbolAddress((void**)&pWkE, g_WkE);
    cudaGetSymbolAddress((void**)&pqp,  g_qp);
    cudaGetSymbolAddress((void**)&pkp,  g_kp);
    cudaGetSymbolAddress((void**)&pV,   g_V);
    cudaGetSymbolAddress((void**)&patt, g_att);
    cudaGetSymbolAddress((void**)&pwp,  g_wp);

    // prep: effective Q/K weights + biases
    prep_eff<<<dim3(8, 8, 2), 256>>>(Wq, Aq, Wk, Ak, bq, bk);

    // Q/K/V projection GEMMs, split-K x2 (6 slices), 128x64 tiles -> 384 CTAs
    gemm_v4<<<dim3(8, 8, 6), 256>>>(query, pWqE, 0, pqp,
                                    key,   pWkE, 0, pkp,
                                    value, Wv,   1, pV,
                                    2, 256);
    reduce_qkv<<<(3*(HALF/4) + 255)/256, 256>>>(bv);

    // fused streaming attention
    attn_kernel<<<dim3(SEQ/32, BATCH*NHEADS), 256>>>(pqp, pkp, pV, av, patt);

    // output projection, split-K x4 -> 256 CTAs
    gemm_v4<<<dim3(8, 8, 4), 256>>>(patt, Wo, 1, pwp,
                                    patt, Wo, 1, pwp,
                                    patt, Wo, 1, pwp,
                                    4, 128);
    reduce_out<<<(HALF/4)/256, 256>>>(out, bo);
}

// round 12
// speedup vs baseline: 2.0701x; 1.0243x over previous
#include <cuda_runtime.h>
#include <cuda_bf16.h>

// Problem constants (fixed by reference)
#define BATCH   2
#define SEQ     512
#define DMODEL  512
#define NHEADS  8
#define DK      64
#define BL      (BATCH*SEQ)   // 1024 rows
#define HALF    (BL*DMODEL)   // one partial buffer (floats)

// ---------------- scratch (device globals; no allocation allowed) ----------
__device__ float g_WqE[DMODEL*DMODEL];
__device__ float g_WkE[DMODEL*DMODEL];
__device__ float g_bqE[DMODEL];
__device__ float g_bkE[DMODEL];
__device__ float g_qp[2*HALF];   // partial 0/1, reduced in place
__device__ float g_kp[2*HALF];
__device__ float g_V [2*HALF];
__device__ float g_att[HALF];
__device__ float g_wp[4*HALF];   // Wo split-K partials

__device__ __forceinline__ float tanh_fast(float x) {
    float y;
    asm("tanh.approx.f32 %0, %1;" : "=f"(y) : "f"(x));
    return y;
}

// ---------------------------------------------------------------------------
// Prep: effective weights via tiled mini-GEMMs (coalesced).
// ---------------------------------------------------------------------------
__global__ __launch_bounds__(256) void prep_eff(
    const float* __restrict__ Wq, const float* __restrict__ Aq,
    const float* __restrict__ Wk, const float* __restrict__ Ak,
    const float* __restrict__ bq, const float* __restrict__ bk) {
    __shared__ float Ws[64*68];   // Ws[d][ii]
    __shared__ float At[64*68];   // At[d][dp]
    int t   = threadIdx.x;
    int it  = blockIdx.x;
    int h   = blockIdx.y;
    int sel = blockIdx.z;
    const float* W = sel ? Wk : Wq;
    const float* A = sel ? Ak : Aq;
    float* WE = sel ? g_WkE : g_WqE;
    const float* bsrc = sel ? bk : bq;
    float* bE = sel ? g_bkE : g_bqE;

    for (int idx = t; idx < 64*64; idx += 256) {
        int d = idx >> 6, ii = idx & 63;
        Ws[d*68 + ii] = W[(h*64 + d)*DMODEL + it*64 + ii];
    }
    for (int idx = t; idx < 64*64; idx += 256) {
        int dp = idx >> 6, d = idx & 63;
        At[d*68 + dp] = A[dp*64 + d];
    }
    __syncthreads();

    int tx = t & 15, ty = t >> 4;
    int dp4 = tx * 4, ii4 = ty * 4;
    float acc[4][4];
#pragma unroll
    for (int i = 0; i < 4; i++)
#pragma unroll
        for (int j = 0; j < 4; j++) acc[i][j] = 0.f;

#pragma unroll 8
    for (int d = 0; d < 64; d++) {
        float4 a4 = *(const float4*)&Ws[d*68 + ii4];
        float4 b4 = *(const float4*)&At[d*68 + dp4];
        float aa[4] = {a4.x, a4.y, a4.z, a4.w};
        float bb[4] = {b4.x, b4.y, b4.z, b4.w};
#pragma unroll
        for (int i = 0; i < 4; i++)
#pragma unroll
            for (int j = 0; j < 4; j++)
                acc[i][j] += aa[i] * bb[j];
    }
#pragma unroll
    for (int i = 0; i < 4; i++) {
        int row = it*64 + ii4 + i;
        *(float4*)&WE[row*DMODEL + h*64 + dp4] =
            make_float4(acc[i][0], acc[i][1], acc[i][2], acc[i][3]);
    }
    if (it == 0 && t < 64) {
        float s = 0.f;
#pragma unroll 8
        for (int d = 0; d < 64; d++)
            s += bsrc[h*64 + d] * At[d*68 + t];
        bE[h*64 + t] = s;
    }
}

// ---------------------------------------------------------------------------
// GEMM v4 (split-K): Cpart = A[:, slice] @ B-slice. M=1024, N=K=512.
// ---------------------------------------------------------------------------
__global__ __launch_bounds__(256) void gemm_v4(
    const float* __restrict__ A0, const float* __restrict__ B0, int t0, float* __restrict__ C0,
    const float* __restrict__ A1, const float* __restrict__ B1, int t1, float* __restrict__ C1,
    const float* __restrict__ A2, const float* __restrict__ B2, int t2, float* __restrict__ C2,
    int nsplit, int KS) {
    const int K = DMODEL, N = DMODEL;
    int z = blockIdx.z;
    int g = z / nsplit, part = z - g * nsplit;
    const float* A  = (g == 0) ? A0 : (g == 1) ? A1 : A2;
    const float* Bm = (g == 0) ? B0 : (g == 1) ? B1 : B2;
    int tb          = (g == 0) ? t0 : (g == 1) ? t1 : t2;
    float* C        = ((g == 0) ? C0 : (g == 1) ? C1 : C2) + part * HALF;
    int kbase = part * KS;

    __shared__ float As[2][16*132];
    __shared__ float Bs[2][16*68];

    int t  = threadIdx.x;          // 256
    int bm = blockIdx.y * 128;
    int bn = blockIdx.x * 64;
    int tx = t & 15, ty = t >> 4;

    float acc[8][4];
#pragma unroll
    for (int i = 0; i < 8; i++)
#pragma unroll
        for (int j = 0; j < 4; j++) acc[i][j] = 0.f;

    int ar0 = t >> 2, akc = (t & 3) << 2;
    int bkr = t >> 4, bnc = (t & 15) << 2;

    float4 ra0, ra1, rb;
    auto fetch = [&](int k0) {
        ra0 = *(const float4*)(A + (bm +      ar0)*K + k0 + akc);
        ra1 = *(const float4*)(A + (bm + 64 + ar0)*K + k0 + akc);
        if (tb == 0)
            rb = *(const float4*)(Bm + (k0 + bkr)*N + bn + bnc);
        else
            rb = *(const float4*)(Bm + (bn + ar0)*K + k0 + akc);
    };
    auto stage = [&](int buf) {
        As[buf][(akc+0)*132 + ar0] = ra0.x;
        As[buf][(akc+1)*132 + ar0] = ra0.y;
        As[buf][(akc+2)*132 + ar0] = ra0.z;
        As[buf][(akc+3)*132 + ar0] = ra0.w;
        As[buf][(akc+0)*132 + 64 + ar0] = ra1.x;
        As[buf][(akc+1)*132 + 64 + ar0] = ra1.y;
        As[buf][(akc+2)*132 + 64 + ar0] = ra1.z;
        As[buf][(akc+3)*132 + 64 + ar0] = ra1.w;
        if (tb == 0) {
            *(float4*)&Bs[buf][bkr*68 + bnc] = rb;
        } else {
            Bs[buf][(akc+0)*68 + ar0] = rb.x;
            Bs[buf][(akc+1)*68 + ar0] = rb.y;
            Bs[buf][(akc+2)*68 + ar0] = rb.z;
            Bs[buf][(akc+3)*68 + ar0] = rb.w;
        }
    };

    fetch(kbase);
    stage(0);
    int cur = 0;
    int kend = kbase + KS;
    for (int k0 = kbase; k0 < kend; k0 += 16) {
        __syncthreads();
        bool more = (k0 + 16) < kend;
        if (more) fetch(k0 + 16);
#pragma unroll
        for (int k = 0; k < 16; k++) {
            float4 aA = *(const float4*)&As[cur][k*132 + ty*8];
            float4 aB = *(const float4*)&As[cur][k*132 + ty*8 + 4];
            float4 b4 = *(const float4*)&Bs[cur][k*68 + tx*4];
            float am[8] = {aA.x, aA.y, aA.z, aA.w, aB.x, aB.y, aB.z, aB.w};
            float bb[4] = {b4.x, b4.y, b4.z, b4.w};
#pragma unroll
            for (int i = 0; i < 8; i++)
#pragma unroll
                for (int j = 0; j < 4; j++)
                    acc[i][j] += am[i] * bb[j];
        }
        if (more) stage(cur ^ 1);
        cur ^= 1;
    }

#pragma unroll
    for (int i = 0; i < 8; i++) {
        int row = bm + ty*8 + i;
        *(float4*)&C[row*N + bn + tx*4] =
            make_float4(acc[i][0], acc[i][1], acc[i][2], acc[i][3]);
    }
}

// ---------------------------------------------------------------------------
// Reduce QKV partials in place: P[f] = P[f] + P[f+HALF] + bias[col]
// ---------------------------------------------------------------------------
__global__ __launch_bounds__(256) void reduce_qkv(
    const float* __restrict__ bv) {
    int idx = blockIdx.x * blockDim.x + threadIdx.x;
    int sel = idx / (HALF/4);
    int f   = idx - sel * (HALF/4);
    float* P = (sel == 0) ? g_qp : (sel == 1) ? g_kp : g_V;
    const float* bias = (sel == 0) ? g_bqE : (sel == 1) ? g_bkE : bv;
    float4 x = *(const float4*)(P + f*4);
    float4 y = *(const float4*)(P + HALF + f*4);
    float4 b = *(const float4*)(bias + (f & 127)*4);
    x.x += y.x + b.x; x.y += y.y + b.y;
    x.z += y.z + b.z; x.w += y.w + b.w;
    *(float4*)(P + f*4) = x;
}

// ---------------------------------------------------------------------------
// Reduce Wo partials: out = wp0+wp1+wp2+wp3 + bo
// ---------------------------------------------------------------------------
__global__ __launch_bounds__(256) void reduce_out(
    float* __restrict__ out, const float* __restrict__ bo) {
    int f = blockIdx.x * blockDim.x + threadIdx.x;
    float4 a = *(const float4*)(g_wp + f*4);
    float4 b = *(const float4*)(g_wp + HALF + f*4);
    float4 c = *(const float4*)(g_wp + 2*HALF + f*4);
    float4 d = *(const float4*)(g_wp + 3*HALF + f*4);
    float4 bb = *(const float4*)(bo + (f & 127)*4);
    float4 o;
    o.x = a.x + b.x + c.x + d.x + bb.x;
    o.y = a.y + b.y + c.y + d.y + bb.y;
    o.z = a.z + b.z + c.z + d.z + bb.z;
    o.w = a.w + b.w + c.w + d.w + bb.w;
    *(float4*)(out + f*4) = o;
}

// ---------------------------------------------------------------------------
// Attention v3 — software-pipelined: phase B (P@V) of tile n-1 runs in the
// SAME barrier segment as phase A (tanh scores) of tile n, so B's FFMA/LDS
// issue in the gaps of A's MUFU-saturated stream. sv/sp double-buffered.
// Softmax without max-subtraction (|s| <= sum|av| ~ 10, exp safe in f32).
// ---------------------------------------------------------------------------
// dynamic smem layout (floats):
#define OFF_SK   0                       // 64*68
#define OFF_SV   (64*68)                 // 2 x 64*68
#define OFF_SP   (OFF_SV + 2*64*68)      // 2 x 32*65
#define OFF_AV   (OFF_SP + 2*32*65)      // 64
#define OFF_PART (OFF_AV + 64)           // 256
#define OFF_INV  (OFF_PART + 256)        // 32
#define ATTN_SMEM ((OFF_INV + 32) * 4)

__global__ __launch_bounds__(256, 2) void attn_kernel(
    const float* __restrict__ qp, const float* __restrict__ kp,
    const float* __restrict__ V,  const float* __restrict__ av,
    float* __restrict__ out) {
    extern __shared__ float smdyn[];
    float* sk     = smdyn + OFF_SK;      // K tile (single buffer)
    float* sv0    = smdyn + OFF_SV;      // V tiles (double)
    float* sv1    = sv0 + 64*68;
    float* sp0    = smdyn + OFF_SP;      // P tiles (double)
    float* sp1    = sp0 + 32*65;
    float* s_av   = smdyn + OFF_AV;
    float* s_part = smdyn + OFF_PART;
    float* s_inv  = smdyn + OFF_INV;

    int t    = threadIdx.x;         // 256
    int lane = t & 31;
    int wid  = t >> 5;
    int i0   = blockIdx.x * 32;
    int bh   = blockIdx.y;
    int b    = bh >> 3, h = bh & 7;
    const int h64 = h * 64;
    const int rowbase = b * SEQ;

    if (t < 64) s_av[t] = av[t];

    // this thread's query row (query = lane) in registers
    float q_r[64];
    {
        const float* qrow = qp + (rowbase + i0 + lane) * DMODEL + h64;
#pragma unroll
        for (int d = 0; d < 64; d += 4) {
            float4 v4 = *(const float4*)(qrow + d);
            q_r[d] = v4.x; q_r[d+1] = v4.y; q_r[d+2] = v4.z; q_r[d+3] = v4.w;
        }
    }

    // phase-B mapping: thread owns 2 queries x 4 d
    int dt = t & 15, ig = t >> 4;
    int d4 = dt << 2;
    int ia = ig << 1;
    float acc0[4] = {0.f, 0.f, 0.f, 0.f};
    float acc1[4] = {0.f, 0.f, 0.f, 0.f};
    float psum = 0.f;

    // tile staging coords
    int frow = t >> 2;
    int fc16 = (t & 3) << 4;

    __syncthreads();                // s_av visible

#pragma unroll 1
    for (int n = 0; n < 8; n++) {
        int jt = n * 64;
        float* svc = (n & 1) ? sv1 : sv0;   // current V buffer
        float* spc = (n & 1) ? sp1 : sp0;   // current P buffer
        float* svp = (n & 1) ? sv0 : sv1;   // previous V buffer
        float* spp = (n & 1) ? sp0 : sp1;   // previous P buffer

        // ---- stage K (single buf) and V (current buf) ----
        {
            const float* ks = kp + (rowbase + jt + frow) * DMODEL + h64 + fc16;
            const float* vs = V  + (rowbase + jt + frow) * DMODEL + h64 + fc16;
            float4 k0 = *(const float4*)(ks + 0);
            float4 k1 = *(const float4*)(ks + 4);
            float4 k2 = *(const float4*)(ks + 8);
            float4 k3 = *(const float4*)(ks + 12);
            float4 v0 = *(const float4*)(vs + 0);
            float4 v1 = *(const float4*)(vs + 4);
            float4 v2 = *(const float4*)(vs + 8);
            float4 v3 = *(const float4*)(vs + 12);
            float* dk = &sk[frow*68 + fc16];
            float* dv = &svc[frow*68 + fc16];
            *(float4*)(dk + 0)  = k0;
            *(float4*)(dk + 4)  = k1;
            *(float4*)(dk + 8)  = k2;
            *(float4*)(dk + 12) = k3;
            *(float4*)(dv + 0)  = v0;
            *(float4*)(dv + 4)  = v1;
            *(float4*)(dv + 8)  = v2;
            *(float4*)(dv + 12) = v3;
        }
        __syncthreads();

        // ---- interleaved: A(tile n) + B(tile n-1) ----
        const float* p0 = &spp[ia*65];
        const float* p1 = &spp[(ia+1)*65];
        bool doB = (n > 0);
#pragma unroll
        for (int jj = 0; jj < 8; jj++) {
            // -- A chunk: one score (j = wid*8+jj) --
            int j = wid * 8 + jj;           // warp-uniform -> broadcast LDS
            const float* krow = &sk[j*68];
            float s = 0.f;
#pragma unroll
            for (int d = 0; d < 64; d += 4) {
                float4 k4 = *(const float4*)(krow + d);
                float4 a4 = *(const float4*)(&s_av[d]);
                s += a4.x * tanh_fast(q_r[d+0] + k4.x);
                s += a4.y * tanh_fast(q_r[d+1] + k4.y);
                s += a4.z * tanh_fast(q_r[d+2] + k4.z);
                s += a4.w * tanh_fast(q_r[d+3] + k4.w);
            }
            float p = __expf(s);            // |s| <= sum|av| ~ 10: safe
            spc[lane*65 + j] = p;
            psum += p;

            // -- B chunk: 8 j's of previous tile --
            if (doB) {
#pragma unroll
                for (int r = 0; r < 8; r++) {
                    int jb = jj*8 + r;
                    float4 v = *(const float4*)&svp[jb*68 + d4];
                    float pa = p0[jb];
                    float pb = p1[jb];
                    acc0[0] += pa * v.x; acc0[1] += pa * v.y;
                    acc0[2] += pa * v.z; acc0[3] += pa * v.w;
                    acc1[0] += pb * v.x; acc1[1] += pb * v.y;
                    acc1[2] += pb * v.z; acc1[3] += pb * v.w;
                }
            }
        }
        __syncthreads();
    }

    // ---- tail: B for tile 7 (buffers of n=7 -> sv1/sp1) ----
    {
        const float* p0 = &sp1[ia*65];
        const float* p1 = &sp1[(ia+1)*65];
#pragma unroll 8
        for (int jb = 0; jb < 64; jb++) {
            float4 v = *(const float4*)&sv1[jb*68 + d4];
            float pa = p0[jb];
            float pb = p1[jb];
            acc0[0] += pa * v.x; acc0[1] += pa * v.y;
            acc0[2] += pa * v.z; acc0[3] += pa * v.w;
            acc1[0] += pb * v.x; acc1[1] += pb * v.y;
            acc1[2] += pb * v.z; acc1[3] += pb * v.w;
        }
    }

    // ---- finalize softmax sums ----
    s_part[wid*32 + lane] = psum;
    __syncthreads();
    if (t < 32) {
        float ssum = 0.f;
#pragma unroll
        for (int w = 0; w < 8; w++) ssum += s_part[w*32 + t];
        s_inv[t] = 1.f / ssum;
    }
    __syncthreads();

    float s0 = s_inv[ia], s1 = s_inv[ia+1];
    float4 o0, o1;
    o0.x = acc0[0]*s0; o0.y = acc0[1]*s0; o0.z = acc0[2]*s0; o0.w = acc0[3]*s0;
    o1.x = acc1[0]*s1; o1.y = acc1[1]*s1; o1.z = acc1[2]*s1; o1.w = acc1[3]*s1;
    *(float4*)&out[(rowbase + i0 + ia    ) * DMODEL + h64 + d4] = o0;
    *(float4*)&out[(rowbase + i0 + ia + 1) * DMODEL + h64 + d4] = o1;
}

// ---------------------------------------------------------------------------
extern "C" void kernel_launch(void* const* d_in, const int* in_sizes, int n_in,
                              void* d_out, int out_size) {
    const float* query = (const float*)d_in[0];
    const float* key   = (const float*)d_in[1];
    const float* value = (const float*)d_in[2];
    const float* Wq    = (const float*)d_in[3];
    const float* bq    = (const float*)d_in[4];
    const float* Wk    = (const float*)d_in[5];
    const float* bk    = (const float*)d_in[6];
    const float* Wv    = (const float*)d_in[7];
    const float* bv    = (const float*)d_in[8];
    const float* Wo    = (const float*)d_in[9];
    const float* bo    = (const float*)d_in[10];
    const float* Aq    = (const float*)d_in[11];
    const float* Ak    = (const float*)d_in[12];
    const float* av    = (const float*)d_in[13];
    float* out = (float*)d_out;

    float *pWqE, *pWkE, *pqp, *pkp, *pV, *patt, *pwp;
    cudaGetSymbolAddress((void**)&pWqE, g_WqE);
    cudaGetSymbolAddress((void**)&pWkE, g_WkE);
    cudaGetSymbolAddress((void**)&pqp,  g_qp);
    cudaGetSymbolAddress((void**)&pkp,  g_kp);
    cudaGetSymbolAddress((void**)&pV,   g_V);
    cudaGetSymbolAddress((void**)&patt, g_att);
    cudaGetSymbolAddress((void**)&pwp,  g_wp);

    cudaFuncSetAttribute(attn_kernel, cudaFuncAttributeMaxDynamicSharedMemorySize, ATTN_SMEM);

    // prep: effective Q/K weights + biases
    prep_eff<<<dim3(8, 8, 2), 256>>>(Wq, Aq, Wk, Ak, bq, bk);

    // Q/K/V projection GEMMs, split-K x2 (6 slices), 128x64 tiles -> 384 CTAs
    gemm_v4<<<dim3(8, 8, 6), 256>>>(query, pWqE, 0, pqp,
                                    key,   pWkE, 0, pkp,
                                    value, Wv,   1, pV,
                                    2, 256);
    reduce_qkv<<<(3*(HALF/4) + 255)/256, 256>>>(bv);

    // fused pipelined attention
    attn_kernel<<<dim3(SEQ/32, BATCH*NHEADS), 256, ATTN_SMEM>>>(pqp, pkp, pV, av, patt);

    // output projection, split-K x4 -> 256 CTAs
    gemm_v4<<<dim3(8, 8, 4), 256>>>(patt, Wo, 1, pwp,
                                    patt, Wo, 1, pwp,
                                    patt, Wo, 1, pwp,
                                    4, 128);
    reduce_out<<<(HALF/4)/256, 256>>>(out, bo);
}